// round 6
// baseline (speedup 1.0000x reference)
#include <cuda_runtime.h>
#include <cuda_fp16.h>
#include <cstdint>

#define Bb 4
#define Nn 2048
#define Cc 256
#define OO 256
#define Ss 32
#define BP (Bb*Nn)            // 8192
#define Ee (BP*Ss)            // 262144
#define K1 259

#define HMINf (-0.02f)
#define HMAXf (0.04f)
#define EPSf  (1e-5f)
#define INVCNT (1.0f/(float)Ee)

// ---------------- static device scratch (allocation-free rule) ----------------
__device__ float  d_W1fT[Cc*OO];            // W1fT[c][o] = W1[o][3+c]
__device__ __half d_W2h [OO*Cc];            // fp16 W2, k-slot-permuted: [o][p(c)]
__device__ int    d_idx [BP*Ss];            // neighbor indices
__device__ __half d_F1h [(size_t)Bb*Nn*OO]; // F1[b][n][o] fp16  (4MB, L2-resident)
__device__ float  d_ps1s[BP*OO], d_ps1q[BP*OO];   // stage-1 partial sums
__device__ float  d_ps2s[BP*OO], d_ps2q[BP*OO];   // stage-2 partial sums
__device__ float  d_mx2 [BP*OO], d_mn2 [BP*OO];   // per-(bp,o) max/min of y2 over s
__device__ float  d_pp  [4*32*OO];                // level-2 partials
__device__ float  d_scale1[OO], d_shift1[OO];
__device__ float  d_scale2[OO], d_shift2[OO];

// k-slot permutation: one thread's 4-half mma fragment = one contiguous 8B load.
__device__ __forceinline__ int kperm(int c){
    int c16 = c & 15;
    int q  = (c16 & 7) >> 1;
    int r  = c16 & 1;
    int hi = (c16 >> 3) & 1;
    return (c & ~15) | (q*4 + hi*2 + r);
}

// ---------------- K0: weight prep ----------------
__global__ void k_wt(const float* __restrict__ W1, const float* __restrict__ W2){
    int i = blockIdx.x*256 + threadIdx.x;      // i = o*256 + c for W2
    int o = i >> 8, c = i & 255;
    d_W1fT[c*OO + o] = W1[o*K1 + 3 + c];
    d_W2h[o*Cc + kperm(c)] = __float2half_rn(W2[i]);
}

// ---------------- K1: cylinder query (one warp per (b,p)) ----------------
__global__ void k_idx(const float* __restrict__ xyz, const float* __restrict__ rot){
    int bp   = blockIdx.x*8 + (threadIdx.x >> 5);
    int lane = threadIdx.x & 31;
    int b = bp >> 11;
    const float* R = rot + (size_t)bp*9;
    float r00=R[0],r01=R[1],r02=R[2],r10=R[3],r11=R[4],r12=R[5],r20=R[6],r21=R[7],r22=R[8];
    const float* cc = xyz + (size_t)bp*3;
    float cx=cc[0], cy=cc[1], cz=cc[2];
    const float R2v = (float)(0.05*0.05);
    int count = 0, firstn = 0;
    bool have = false;
    for (int base = 0; base < Nn && count < Ss; base += 32){
        int n = base + lane;
        const float* q = xyz + ((size_t)b*Nn + n)*3;
        float dx=q[0]-cx, dy=q[1]-cy, dz=q[2]-cz;
        float a0 = r00*dx + r01*dy + r02*dz;
        float a1 = r10*dx + r11*dy + r12*dz;
        float a2 = r20*dx + r21*dy + r22*dz;
        bool m = (a1*a1 + a2*a2 < R2v) & (a0 > HMINf) & (a0 < HMAXf);
        unsigned bal = __ballot_sync(0xffffffffu, m);
        if (!have && bal){ firstn = base + (__ffs(bal) - 1); have = true; }
        int pre = __popc(bal & ((1u << lane) - 1u));
        if (m && count + pre < Ss) d_idx[bp*Ss + count + pre] = n;
        count += __popc(bal);
    }
    if (count < Ss){
        for (int j = count + lane; j < Ss; j += 32) d_idx[bp*Ss + j] = firstn;
    }
}

// ---------------- K2: F1 = W1_feat @ feat (fp32 compute, fp16 store) ----------------
__global__ void __launch_bounds__(256) k_F1(const float* __restrict__ feat){
    int b  = blockIdx.y;
    int n0 = blockIdx.x * 32;
    __shared__ __align__(16) float fsh[32][32];
    int tid = threadIdx.x;
    int o = tid;
    float acc[32];
    #pragma unroll
    for (int n = 0; n < 32; n++) acc[n] = 0.f;

    for (int ck = 0; ck < 8; ck++){
        #pragma unroll
        for (int r = 0; r < 4; r++){
            int li = tid + r*256;
            int ci = li >> 5, nj = li & 31;
            fsh[ci][nj] = feat[((size_t)b*Cc + ck*32 + ci)*Nn + n0 + nj];
        }
        __syncthreads();
        #pragma unroll 4
        for (int ci2 = 0; ci2 < 32; ci2++){
            float w = d_W1fT[(ck*32 + ci2)*OO + o];
            const float4* row = reinterpret_cast<const float4*>(&fsh[ci2][0]);
            #pragma unroll
            for (int nq = 0; nq < 8; nq++){
                float4 f = row[nq];
                acc[4*nq+0] = fmaf(f.x, w, acc[4*nq+0]);
                acc[4*nq+1] = fmaf(f.y, w, acc[4*nq+1]);
                acc[4*nq+2] = fmaf(f.z, w, acc[4*nq+2]);
                acc[4*nq+3] = fmaf(f.w, w, acc[4*nq+3]);
            }
        }
        __syncthreads();
    }
    #pragma unroll
    for (int n = 0; n < 32; n++)
        d_F1h[((size_t)b*Nn + n0 + n)*OO + o] = __float2half_rn(acc[n]);
}

// ---------------- K3: stats of conv1 output (no materialization) ----------------
__global__ void __launch_bounds__(256) k_stats1(const float* __restrict__ xyz,
                                                const float* __restrict__ rot,
                                                const float* __restrict__ W1){
    int bp = blockIdx.x;
    int b = bp >> 11;
    __shared__ int   idxs[32];
    __shared__ float gx[32], gy[32], gz[32];
    int tid = threadIdx.x;
    if (tid < 32){
        int s = tid;
        int i = d_idx[bp*Ss + s];
        idxs[s] = i;
        const float* R = rot + (size_t)bp*9;
        const float* c = xyz + (size_t)bp*3;
        const float* q = xyz + ((size_t)b*Nn + i)*3;
        float vx = (q[0]-c[0]) / 0.05f;
        float vy = (q[1]-c[1]) / 0.05f;
        float vz = (q[2]-c[2]) / 0.05f;
        gx[s] = vx*R[0] + vy*R[3] + vz*R[6];
        gy[s] = vx*R[1] + vy*R[4] + vz*R[7];
        gz[s] = vx*R[2] + vy*R[5] + vz*R[8];
    }
    __syncthreads();

    int o = tid;
    float w0 = W1[o*K1+0], w1 = W1[o*K1+1], w2 = W1[o*K1+2];
    const __half* F1b = d_F1h + (size_t)b*Nn*OO;
    float lsum = 0.f, lsq = 0.f;
    #pragma unroll 8
    for (int s = 0; s < Ss; s++){
        float v = __half2float(F1b[(size_t)idxs[s]*OO + o]);
        v = fmaf(w0, gx[s], fmaf(w1, gy[s], fmaf(w2, gz[s], v)));
        lsum += v;
        lsq  = fmaf(v, v, lsq);
    }
    d_ps1s[bp*OO + o] = lsum;
    d_ps1q[bp*OO + o] = lsq;
}

// ---------------- deterministic two-level reduction ----------------
__global__ void k_red_a(int base){
    int which = base + blockIdx.y;               // 0..3
    const float* src = (which == 0) ? d_ps1s : (which == 1) ? d_ps1q
                     : (which == 2) ? d_ps2s : d_ps2q;
    float* dst = d_pp + which*(32*OO);
    int z = blockIdx.x;                          // 0..31
    int o = threadIdx.x;
    float s = 0.f;
    for (int k = 0; k < 256; k++)
        s += src[((size_t)(z*256 + k))*OO + o];
    dst[z*OO + o] = s;
}

__global__ void k_red_b(int stage, const float* __restrict__ gamma,
                        const float* __restrict__ beta){
    int o = threadIdx.x;
    const float* pps = d_pp + (2*stage + 0)*(32*OO);
    const float* ppq = d_pp + (2*stage + 1)*(32*OO);
    float s = 0.f, q = 0.f;
    for (int z = 0; z < 32; z++){ s += pps[z*OO + o]; q += ppq[z*OO + o]; }
    float mu  = s * INVCNT;
    float var = q * INVCNT - mu*mu;
    float sc  = rsqrtf(var + EPSf) * gamma[o];
    float sf  = beta[o] - mu*sc;
    if (stage == 0){ d_scale1[o] = sc; d_shift1[o] = sf; }
    else           { d_scale2[o] = sc; d_shift2[o] = sf; }
}

// ---------------- fp16 mma helper ----------------
__device__ __forceinline__ void mma_f16(float& d0, float& d1, float& d2, float& d3,
                                        uint32_t a0, uint32_t a1, uint32_t a2, uint32_t a3,
                                        uint32_t b0, uint32_t b1){
    asm volatile("mma.sync.aligned.m16n8k16.row.col.f32.f16.f16.f32 "
                 "{%0,%1,%2,%3}, {%4,%5,%6,%7}, {%8,%9}, {%0,%1,%2,%3};\n"
                 : "+f"(d0), "+f"(d1), "+f"(d2), "+f"(d3)
                 : "r"(a0), "r"(a1), "r"(a2), "r"(a3), "r"(b0), "r"(b1));
}

#define HSTR 264   // halfs: 132 words == 4 (mod 32) -> conflict-free LDS.64 B loads

// ---------------- K4: conv2, fp16 tensor cores, 4 bp per block, stats epilogue ----------------
__global__ void __launch_bounds__(512) k_conv2(const float* __restrict__ xyz,
                                               const float* __restrict__ rot,
                                               const float* __restrict__ W1){
    extern __shared__ __align__(16) char smraw[];
    __half* h16  = (__half*)smraw;                       // [128][HSTR]
    int*    idxs = (int*)(smraw + 128*HSTR*2);           // [128]
    float*  gxx  = (float*)(idxs + 128);
    float*  gyy  = gxx + 128;
    float*  gzz  = gyy + 128;

    int tid = threadIdx.x;
    int bp0 = blockIdx.x * 4;                            // 4 bp per block, same batch
    int b   = bp0 >> 11;

    // --- geometry for 4 bp's (128 samples) ---
    if (tid < 128){
        int s  = tid;
        int bp = bp0 + (s >> 5);
        int i  = d_idx[bp*Ss + (s & 31)];
        idxs[s] = i;
        const float* R = rot + (size_t)bp*9;
        const float* c = xyz + (size_t)bp*3;
        const float* q = xyz + ((size_t)b*Nn + i)*3;
        float vx = (q[0]-c[0]) / 0.05f;
        float vy = (q[1]-c[1]) / 0.05f;
        float vz = (q[2]-c[2]) / 0.05f;
        gxx[s] = vx*R[0] + vy*R[3] + vz*R[6];
        gyy[s] = vx*R[1] + vy*R[4] + vz*R[7];
        gzz[s] = vx*R[2] + vy*R[5] + vz*R[8];
    }
    __syncthreads();

    // --- build h tile: h[s][kperm(c)] = fp16(relu(BN1(y1))) ---
    {
        int c     = tid & 255;
        int sbase = (tid >> 8) * 64;
        int p     = kperm(c);
        float w0 = W1[c*K1+0], w1 = W1[c*K1+1], w2 = W1[c*K1+2];
        float sc = d_scale1[c], sf = d_shift1[c];
        const __half* F1b = d_F1h + (size_t)b*Nn*OO;
        #pragma unroll 8
        for (int ds = 0; ds < 64; ds++){
            int s = sbase + ds;
            float v = __half2float(F1b[(size_t)idxs[s]*OO + c]);
            v = fmaf(w0, gxx[s], fmaf(w1, gyy[s], fmaf(w2, gzz[s], v)));
            v = fmaxf(fmaf(v, sc, sf), 0.f);
            h16[s*HSTR + p] = __float2half_rn(v);
        }
    }
    __syncthreads();

    // --- tensor-core GEMM: D[o,s] = sum_c W2[o,c] * h[s,c] ---
    int lane = tid & 31, w = tid >> 5;
    int q = lane & 3, g = lane >> 2;
    int obase = (w & 7) * 32;                    // 8 warps cover 256 o
    int warpS = (w >> 3) * 64;                   // 2 warp-rows cover 128 s

    // A: single base pointer; rows +8/+16/+24 as immediate offsets (+512/+1024/+1536 uint2)
    const uint2* Ab = (const uint2*)(d_W2h + (size_t)(obase + g)*Cc);
    // B: single smem base; j as immediate offsets
    const char* Bsm = (const char*)h16 + (size_t)(warpS + g)*HSTR*2;

    float acc[2][8][4];
    #pragma unroll
    for (int i = 0; i < 2; i++)
        #pragma unroll
        for (int j = 0; j < 8; j++)
            #pragma unroll
            for (int k = 0; k < 4; k++) acc[i][j][k] = 0.f;

    uint2 a0 = Ab[q], a1 = Ab[q+512], a2 = Ab[q+1024], a3 = Ab[q+1536];
    #pragma unroll
    for (int kt = 0; kt < 16; kt++){
        uint2 na0, na1, na2, na3;
        if (kt < 15){
            int ko2 = (kt+1)*4 + q;
            na0 = Ab[ko2]; na1 = Ab[ko2+512]; na2 = Ab[ko2+1024]; na3 = Ab[ko2+1536];
        }
        int ko = kt*4 + q;
        #pragma unroll
        for (int j = 0; j < 8; j++){
            uint2 bv = *(const uint2*)(Bsm + j*(8*HSTR*2) + ko*8);
            mma_f16(acc[0][j][0], acc[0][j][1], acc[0][j][2], acc[0][j][3],
                    a0.x, a1.x, a0.y, a1.y, bv.x, bv.y);
            mma_f16(acc[1][j][0], acc[1][j][1], acc[1][j][2], acc[1][j][3],
                    a2.x, a3.x, a2.y, a3.y, bv.x, bv.y);
        }
        if (kt < 15){ a0 = na0; a1 = na1; a2 = na2; a3 = na3; }
    }

    // --- epilogue: per-(bp,o) sum / sumsq / max / min over that bp's 32 s ---
    #pragma unroll
    for (int half = 0; half < 2; half++){
        int bp = bp0 + 2*(w >> 3) + half;
        #pragma unroll
        for (int i = 0; i < 2; i++){
            float s0=0.f, q0=0.f, mx0=-3.4e38f, mn0=3.4e38f;   // row g
            float s1=0.f, q1=0.f, mx1=-3.4e38f, mn1=3.4e38f;   // row g+8
            #pragma unroll
            for (int j4 = 0; j4 < 4; j4++){
                const float* a = acc[i][half*4 + j4];
                s0 += a[0] + a[1];
                q0  = fmaf(a[0], a[0], fmaf(a[1], a[1], q0));
                mx0 = fmaxf(mx0, fmaxf(a[0], a[1]));
                mn0 = fminf(mn0, fminf(a[0], a[1]));
                s1 += a[2] + a[3];
                q1  = fmaf(a[2], a[2], fmaf(a[3], a[3], q1));
                mx1 = fmaxf(mx1, fmaxf(a[2], a[3]));
                mn1 = fminf(mn1, fminf(a[2], a[3]));
            }
            #pragma unroll
            for (int msk = 1; msk <= 2; msk <<= 1){
                s0 += __shfl_xor_sync(0xffffffffu, s0, msk);
                q0 += __shfl_xor_sync(0xffffffffu, q0, msk);
                mx0 = fmaxf(mx0, __shfl_xor_sync(0xffffffffu, mx0, msk));
                mn0 = fminf(mn0, __shfl_xor_sync(0xffffffffu, mn0, msk));
                s1 += __shfl_xor_sync(0xffffffffu, s1, msk);
                q1 += __shfl_xor_sync(0xffffffffu, q1, msk);
                mx1 = fmaxf(mx1, __shfl_xor_sync(0xffffffffu, mx1, msk));
                mn1 = fminf(mn1, __shfl_xor_sync(0xffffffffu, mn1, msk));
            }
            if (q == 0){
                int o0 = obase + 16*i + g;
                size_t ix0 = (size_t)bp*OO + o0;
                d_ps2s[ix0] = s0; d_ps2q[ix0] = q0; d_mx2[ix0] = mx0; d_mn2[ix0] = mn0;
                size_t ix1 = ix0 + 8;
                d_ps2s[ix1] = s1; d_ps2q[ix1] = q1; d_mx2[ix1] = mx1; d_mn2[ix1] = mn1;
            }
        }
    }
}

// ---------------- K5: BN2 + relu + max via monotonicity, transpose-write ----------------
__global__ void __launch_bounds__(256) k_final(float* __restrict__ out){
    int blk = blockIdx.x;                 // 256 blocks, 32 p's each
    int bp0 = blk * 32;
    int b = bp0 >> 11;
    int pbase = bp0 & 2047;
    int tid = threadIdx.x;
    __shared__ float sh[256*33];

    int o = tid;
    float sc = d_scale2[o], sf = d_shift2[o];
    for (int p = 0; p < 32; p++){
        size_t ix = (size_t)(bp0 + p)*OO + o;
        float mx = d_mx2[ix], mn = d_mn2[ix];
        float m = (sc >= 0.f) ? mx : mn;
        sh[o*33 + p] = fmaxf(fmaf(m, sc, sf), 0.f);
    }
    __syncthreads();

    int p   = tid & 31;
    int og0 = (tid >> 5) * 32;
    #pragma unroll
    for (int k = 0; k < 32; k++){
        int o2 = og0 + k;
        out[((size_t)(b*OO + o2))*Nn + pbase + p] = sh[o2*33 + p];
    }
}

// ---------------- launcher ----------------
extern "C" void kernel_launch(void* const* d_in, const int* in_sizes, int n_in,
                              void* d_out, int out_size){
    (void)in_sizes; (void)n_in; (void)out_size;
    const float* xyz  = (const float*)d_in[0];
    const float* feat = (const float*)d_in[1];
    const float* rot  = (const float*)d_in[2];
    const float* W1   = (const float*)d_in[3];
    const float* g1   = (const float*)d_in[4];
    const float* b1   = (const float*)d_in[5];
    const float* W2   = (const float*)d_in[6];
    const float* g2   = (const float*)d_in[7];
    const float* b2   = (const float*)d_in[8];
    float* out = (float*)d_out;

    const int SMEMB = 128*HSTR*2 + 128*4*4;   // 67584 + 2048 = 69632 B
    cudaFuncSetAttribute(k_conv2, cudaFuncAttributeMaxDynamicSharedMemorySize, SMEMB);

    k_wt    <<<256, 256>>>(W1, W2);
    k_idx   <<<BP/8, 256>>>(xyz, rot);
    k_F1    <<<dim3(Nn/32, Bb), 256>>>(feat);
    k_stats1<<<BP, 256>>>(xyz, rot, W1);
    k_red_a <<<dim3(32,2), 256>>>(0);
    k_red_b <<<1, 256>>>(0, g1, b1);
    k_conv2 <<<BP/4, 512, SMEMB>>>(xyz, rot, W1);
    k_red_a <<<dim3(32,2), 256>>>(2);
    k_red_b <<<1, 256>>>(1, g2, b2);
    k_final <<<BP/32, 256>>>(out);
}

// round 7
// speedup vs baseline: 1.3337x; 1.3337x over previous
#include <cuda_runtime.h>
#include <cuda_fp16.h>
#include <cstdint>

#define Bb 4
#define Nn 2048
#define Cc 256
#define OO 256
#define Ss 32
#define BP (Bb*Nn)            // 8192
#define Ee (BP*Ss)            // 262144
#define K1 259

#define HMINf (-0.02f)
#define HMAXf (0.04f)
#define EPSf  (1e-5f)
#define INVCNT (1.0f/(float)Ee)

// ---------------- static device scratch (allocation-free rule) ----------------
__device__ float  d_W1fT[Cc*OO];            // W1fT[c][o] = W1[o][3+c]
__device__ __half d_W2h [OO*Cc];            // fp16 W2, k-slot-permuted: [o][p(c)]
__device__ int    d_idx [BP*Ss];            // neighbor indices
__device__ __half d_F1h [(size_t)Bb*Nn*OO]; // F1[b][n][o] fp16  (4MB, L2-resident)
__device__ float  d_ps1s[BP*OO], d_ps1q[BP*OO];   // stage-1 partial sums
__device__ float  d_ps2s[BP*OO], d_ps2q[BP*OO];   // stage-2 partial sums
__device__ float  d_mx2 [BP*OO], d_mn2 [BP*OO];   // per-(bp,o) max/min of y2 over s
__device__ float  d_pp  [4*32*OO];                // level-2 partials
__device__ float  d_scale1[OO], d_shift1[OO];
__device__ float  d_scale2[OO], d_shift2[OO];

// k-slot permutation: one thread's 4-half mma fragment = one contiguous 8B load.
// Pairs (2k, 2k+1) stay adjacent: kperm(c even) is even, kperm(c+1)=kperm(c)+1.
__device__ __forceinline__ int kperm(int c){
    int c16 = c & 15;
    int q  = (c16 & 7) >> 1;
    int r  = c16 & 1;
    int hi = (c16 >> 3) & 1;
    return (c & ~15) | (q*4 + hi*2 + r);
}

// ---------------- K0: weight prep ----------------
__global__ void k_wt(const float* __restrict__ W1, const float* __restrict__ W2){
    int i = blockIdx.x*256 + threadIdx.x;      // i = o*256 + c for W2
    int o = i >> 8, c = i & 255;
    d_W1fT[c*OO + o] = W1[o*K1 + 3 + c];
    d_W2h[o*Cc + kperm(c)] = __float2half_rn(W2[i]);
}

// ---------------- K1: cylinder query (one warp per (b,p)) ----------------
__global__ void k_idx(const float* __restrict__ xyz, const float* __restrict__ rot){
    int bp   = blockIdx.x*8 + (threadIdx.x >> 5);
    int lane = threadIdx.x & 31;
    int b = bp >> 11;
    const float* R = rot + (size_t)bp*9;
    float r00=R[0],r01=R[1],r02=R[2],r10=R[3],r11=R[4],r12=R[5],r20=R[6],r21=R[7],r22=R[8];
    const float* cc = xyz + (size_t)bp*3;
    float cx=cc[0], cy=cc[1], cz=cc[2];
    const float R2v = (float)(0.05*0.05);
    int count = 0, firstn = 0;
    bool have = false;
    for (int base = 0; base < Nn && count < Ss; base += 32){
        int n = base + lane;
        const float* q = xyz + ((size_t)b*Nn + n)*3;
        float dx=q[0]-cx, dy=q[1]-cy, dz=q[2]-cz;
        float a0 = r00*dx + r01*dy + r02*dz;
        float a1 = r10*dx + r11*dy + r12*dz;
        float a2 = r20*dx + r21*dy + r22*dz;
        bool m = (a1*a1 + a2*a2 < R2v) & (a0 > HMINf) & (a0 < HMAXf);
        unsigned bal = __ballot_sync(0xffffffffu, m);
        if (!have && bal){ firstn = base + (__ffs(bal) - 1); have = true; }
        int pre = __popc(bal & ((1u << lane) - 1u));
        if (m && count + pre < Ss) d_idx[bp*Ss + count + pre] = n;
        count += __popc(bal);
    }
    if (count < Ss){
        for (int j = count + lane; j < Ss; j += 32) d_idx[bp*Ss + j] = firstn;
    }
}

// ---------------- K2: F1 = W1_feat @ feat (fp32 compute, fp16 store) ----------------
__global__ void __launch_bounds__(256) k_F1(const float* __restrict__ feat){
    int b  = blockIdx.y;
    int n0 = blockIdx.x * 32;
    __shared__ __align__(16) float fsh[32][32];
    int tid = threadIdx.x;
    int o = tid;
    float acc[32];
    #pragma unroll
    for (int n = 0; n < 32; n++) acc[n] = 0.f;

    for (int ck = 0; ck < 8; ck++){
        #pragma unroll
        for (int r = 0; r < 4; r++){
            int li = tid + r*256;
            int ci = li >> 5, nj = li & 31;
            fsh[ci][nj] = feat[((size_t)b*Cc + ck*32 + ci)*Nn + n0 + nj];
        }
        __syncthreads();
        #pragma unroll 4
        for (int ci2 = 0; ci2 < 32; ci2++){
            float w = d_W1fT[(ck*32 + ci2)*OO + o];
            const float4* row = reinterpret_cast<const float4*>(&fsh[ci2][0]);
            #pragma unroll
            for (int nq = 0; nq < 8; nq++){
                float4 f = row[nq];
                acc[4*nq+0] = fmaf(f.x, w, acc[4*nq+0]);
                acc[4*nq+1] = fmaf(f.y, w, acc[4*nq+1]);
                acc[4*nq+2] = fmaf(f.z, w, acc[4*nq+2]);
                acc[4*nq+3] = fmaf(f.w, w, acc[4*nq+3]);
            }
        }
        __syncthreads();
    }
    #pragma unroll
    for (int n = 0; n < 32; n++)
        d_F1h[((size_t)b*Nn + n0 + n)*OO + o] = __float2half_rn(acc[n]);
}

// ---------------- K3: stats of conv1 output, half2 (128 threads = 2 o's each) ----------
__global__ void __launch_bounds__(128) k_stats1(const float* __restrict__ xyz,
                                                const float* __restrict__ rot,
                                                const float* __restrict__ W1){
    int bp = blockIdx.x;
    int b = bp >> 11;
    __shared__ int   idxs[32];
    __shared__ float gx[32], gy[32], gz[32];
    int tid = threadIdx.x;
    if (tid < 32){
        int s = tid;
        int i = d_idx[bp*Ss + s];
        idxs[s] = i;
        const float* R = rot + (size_t)bp*9;
        const float* c = xyz + (size_t)bp*3;
        const float* q = xyz + ((size_t)b*Nn + i)*3;
        float vx = (q[0]-c[0]) / 0.05f;
        float vy = (q[1]-c[1]) / 0.05f;
        float vz = (q[2]-c[2]) / 0.05f;
        gx[s] = vx*R[0] + vy*R[3] + vz*R[6];
        gy[s] = vx*R[1] + vy*R[4] + vz*R[7];
        gz[s] = vx*R[2] + vy*R[5] + vz*R[8];
    }
    __syncthreads();

    int c0 = tid*2;
    float wa0 = W1[c0*K1+0],     wa1 = W1[c0*K1+1],     wa2 = W1[c0*K1+2];
    float wb0 = W1[(c0+1)*K1+0], wb1 = W1[(c0+1)*K1+1], wb2 = W1[(c0+1)*K1+2];
    const __half2* F1b2 = (const __half2*)(d_F1h + (size_t)b*Nn*OO);
    float lsa = 0.f, lqa = 0.f, lsb = 0.f, lqb = 0.f;
    #pragma unroll 8
    for (int s = 0; s < Ss; s++){
        __half2 hv = F1b2[(size_t)idxs[s]*128 + tid];
        float2 f = __half22float2(hv);
        float va = fmaf(wa0, gx[s], fmaf(wa1, gy[s], fmaf(wa2, gz[s], f.x)));
        float vb = fmaf(wb0, gx[s], fmaf(wb1, gy[s], fmaf(wb2, gz[s], f.y)));
        lsa += va;  lqa = fmaf(va, va, lqa);
        lsb += vb;  lqb = fmaf(vb, vb, lqb);
    }
    d_ps1s[bp*OO + c0]     = lsa;  d_ps1q[bp*OO + c0]     = lqa;
    d_ps1s[bp*OO + c0 + 1] = lsb;  d_ps1q[bp*OO + c0 + 1] = lqb;
}

// ---------------- deterministic two-level reduction ----------------
__global__ void k_red_a(int base){
    int which = base + blockIdx.y;               // 0..3
    const float* src = (which == 0) ? d_ps1s : (which == 1) ? d_ps1q
                     : (which == 2) ? d_ps2s : d_ps2q;
    float* dst = d_pp + which*(32*OO);
    int z = blockIdx.x;                          // 0..31
    int o = threadIdx.x;
    float s = 0.f;
    for (int k = 0; k < 256; k++)
        s += src[((size_t)(z*256 + k))*OO + o];
    dst[z*OO + o] = s;
}

__global__ void k_red_b(int stage, const float* __restrict__ gamma,
                        const float* __restrict__ beta){
    int o = threadIdx.x;
    const float* pps = d_pp + (2*stage + 0)*(32*OO);
    const float* ppq = d_pp + (2*stage + 1)*(32*OO);
    float s = 0.f, q = 0.f;
    for (int z = 0; z < 32; z++){ s += pps[z*OO + o]; q += ppq[z*OO + o]; }
    float mu  = s * INVCNT;
    float var = q * INVCNT - mu*mu;
    float sc  = rsqrtf(var + EPSf) * gamma[o];
    float sf  = beta[o] - mu*sc;
    if (stage == 0){ d_scale1[o] = sc; d_shift1[o] = sf; }
    else           { d_scale2[o] = sc; d_shift2[o] = sf; }
}

// ---------------- fp16 mma helper ----------------
__device__ __forceinline__ void mma_f16(float& d0, float& d1, float& d2, float& d3,
                                        uint32_t a0, uint32_t a1, uint32_t a2, uint32_t a3,
                                        uint32_t b0, uint32_t b1){
    asm volatile("mma.sync.aligned.m16n8k16.row.col.f32.f16.f16.f32 "
                 "{%0,%1,%2,%3}, {%4,%5,%6,%7}, {%8,%9}, {%0,%1,%2,%3};\n"
                 : "+f"(d0), "+f"(d1), "+f"(d2), "+f"(d3)
                 : "r"(a0), "r"(a1), "r"(a2), "r"(a3), "r"(b0), "r"(b1));
}

#define HSTR 272   // halfs: 136 words == 8 (mod 32) -> conflict-free LDS.64 (per 16-lane phase)
#define ASTR 80    // A smem row stride (halfs): 40 words == 8 (mod 32) -> conflict-free
#define ABUF (256*ASTR)          // halfs per A buffer (20480 = 40960 B)
#define SM_A   (128*HSTR*2)                    // 69632
#define SM_IDX (SM_A + 2*ABUF*2)               // 69632 + 81920 = 151552
#define SMEMB  (SM_IDX + 128*4*4)              // 153600

// cp.async one A chunk (64 channels = 4 kt) into buf; 512 threads x 4 x 16B
__device__ __forceinline__ void load_A_chunk(__half* buf, int ch, int tid){
    #pragma unroll
    for (int k = 0; k < 4; k++){
        int i   = tid + k*512;          // 0..2047
        int row = i >> 3, seg = i & 7;  // 256 rows x 8 x 16B
        uint32_t d = (uint32_t)__cvta_generic_to_shared(buf + row*ASTR + seg*8);
        const __half* src = d_W2h + row*Cc + ch*64 + seg*8;
        asm volatile("cp.async.cg.shared.global [%0], [%1], 16;\n" :: "r"(d), "l"(src));
    }
}

// ---------------- K4: conv2, fp16 mma, smem-staged A (cp.async), 4 bp/block ----------------
__global__ void __launch_bounds__(512) k_conv2(const float* __restrict__ xyz,
                                               const float* __restrict__ rot,
                                               const float* __restrict__ W1){
    extern __shared__ __align__(16) char smraw[];
    __half* h16  = (__half*)smraw;                       // [128][HSTR]
    __half* Asm  = (__half*)(smraw + SM_A);              // 2 x [256][ASTR]
    int*    idxs = (int*)(smraw + SM_IDX);               // [128]
    float*  gxx  = (float*)(idxs + 128);
    float*  gyy  = gxx + 128;
    float*  gzz  = gyy + 128;

    int tid = threadIdx.x;
    int bp0 = blockIdx.x * 4;                            // 4 bp per block, same batch
    int b   = bp0 >> 11;

    // start A chunk 0 immediately (overlaps geometry + h-build)
    load_A_chunk(Asm, 0, tid);
    asm volatile("cp.async.commit_group;\n" ::: "memory");

    // --- geometry for 4 bp's (128 samples) ---
    if (tid < 128){
        int s  = tid;
        int bp = bp0 + (s >> 5);
        int i  = d_idx[bp*Ss + (s & 31)];
        idxs[s] = i;
        const float* R = rot + (size_t)bp*9;
        const float* c = xyz + (size_t)bp*3;
        const float* q = xyz + ((size_t)b*Nn + i)*3;
        float vx = (q[0]-c[0]) / 0.05f;
        float vy = (q[1]-c[1]) / 0.05f;
        float vz = (q[2]-c[2]) / 0.05f;
        gxx[s] = vx*R[0] + vy*R[3] + vz*R[6];
        gyy[s] = vx*R[1] + vy*R[4] + vz*R[7];
        gzz[s] = vx*R[2] + vy*R[5] + vz*R[8];
    }
    __syncthreads();

    // --- build h tile (half2: 2 channels per thread, 32 s each) ---
    {
        int cpair = tid & 127;              // c = 2*cpair, 2*cpair+1
        int c0    = cpair*2;
        int sbase = (tid >> 7) * 32;        // 4 groups x 32 s
        int p     = kperm(c0);              // even; pair -> (p, p+1)
        float wa0 = W1[c0*K1+0],     wa1 = W1[c0*K1+1],     wa2 = W1[c0*K1+2];
        float wb0 = W1[(c0+1)*K1+0], wb1 = W1[(c0+1)*K1+1], wb2 = W1[(c0+1)*K1+2];
        float sca = d_scale1[c0],   sfa = d_shift1[c0];
        float scb = d_scale1[c0+1], sfb = d_shift1[c0+1];
        const __half2* F1b2 = (const __half2*)(d_F1h + (size_t)b*Nn*OO);
        #pragma unroll 8
        for (int ds = 0; ds < 32; ds++){
            int s = sbase + ds;
            float2 f = __half22float2(F1b2[(size_t)idxs[s]*128 + cpair]);
            float va = fmaf(wa0, gxx[s], fmaf(wa1, gyy[s], fmaf(wa2, gzz[s], f.x)));
            float vb = fmaf(wb0, gxx[s], fmaf(wb1, gyy[s], fmaf(wb2, gzz[s], f.y)));
            va = fmaxf(fmaf(va, sca, sfa), 0.f);
            vb = fmaxf(fmaf(vb, scb, sfb), 0.f);
            *(__half2*)(h16 + s*HSTR + p) = __floats2half2_rn(va, vb);
        }
    }
    __syncthreads();

    // --- tensor-core GEMM: D[o,s] = sum_c W2[o,c] * h[s,c], A staged in smem ---
    int lane = tid & 31, w = tid >> 5;
    int q = lane & 3, g = lane >> 2;
    int obase = (w & 7) * 32;                    // 8 warps cover 256 o
    int warpS = (w >> 3) * 64;                   // 2 warp-rows cover 128 s

    const char* Bsm = (const char*)h16 + (size_t)(warpS + g)*HSTR*2;

    float acc[2][8][4];
    #pragma unroll
    for (int i = 0; i < 2; i++)
        #pragma unroll
        for (int j = 0; j < 8; j++)
            #pragma unroll
            for (int k = 0; k < 4; k++) acc[i][j][k] = 0.f;

    #pragma unroll
    for (int ch = 0; ch < 4; ch++){
        if (ch < 3){
            load_A_chunk(Asm + ((ch+1)&1)*ABUF, ch+1, tid);
            asm volatile("cp.async.commit_group;\n" ::: "memory");
            asm volatile("cp.async.wait_group 1;\n" ::: "memory");
        } else {
            asm volatile("cp.async.wait_group 0;\n" ::: "memory");
        }
        __syncthreads();

        const char* Arow = (const char*)(Asm + (ch&1)*ABUF + (size_t)(obase + g)*ASTR);
        #pragma unroll
        for (int ktl = 0; ktl < 4; ktl++){
            uint2 fa0 = *(const uint2*)(Arow +            0 + ktl*32 + q*8);
            uint2 fa1 = *(const uint2*)(Arow +  8*ASTR*2     + ktl*32 + q*8);
            uint2 fa2 = *(const uint2*)(Arow + 16*ASTR*2     + ktl*32 + q*8);
            uint2 fa3 = *(const uint2*)(Arow + 24*ASTR*2     + ktl*32 + q*8);
            #pragma unroll
            for (int j = 0; j < 8; j++){
                uint2 bv = *(const uint2*)(Bsm + j*(8*HSTR*2) + (ch*4 + ktl)*32 + q*8);
                mma_f16(acc[0][j][0], acc[0][j][1], acc[0][j][2], acc[0][j][3],
                        fa0.x, fa1.x, fa0.y, fa1.y, bv.x, bv.y);
                mma_f16(acc[1][j][0], acc[1][j][1], acc[1][j][2], acc[1][j][3],
                        fa2.x, fa3.x, fa2.y, fa3.y, bv.x, bv.y);
            }
        }
        __syncthreads();
    }

    // --- epilogue: per-(bp,o) sum / sumsq / max / min over that bp's 32 s ---
    #pragma unroll
    for (int half = 0; half < 2; half++){
        int bp = bp0 + 2*(w >> 3) + half;
        #pragma unroll
        for (int i = 0; i < 2; i++){
            float s0=0.f, q0=0.f, mx0=-3.4e38f, mn0=3.4e38f;   // row g
            float s1=0.f, q1=0.f, mx1=-3.4e38f, mn1=3.4e38f;   // row g+8
            #pragma unroll
            for (int j4 = 0; j4 < 4; j4++){
                const float* a = acc[i][half*4 + j4];
                s0 += a[0] + a[1];
                q0  = fmaf(a[0], a[0], fmaf(a[1], a[1], q0));
                mx0 = fmaxf(mx0, fmaxf(a[0], a[1]));
                mn0 = fminf(mn0, fminf(a[0], a[1]));
                s1 += a[2] + a[3];
                q1  = fmaf(a[2], a[2], fmaf(a[3], a[3], q1));
                mx1 = fmaxf(mx1, fmaxf(a[2], a[3]));
                mn1 = fminf(mn1, fminf(a[2], a[3]));
            }
            #pragma unroll
            for (int msk = 1; msk <= 2; msk <<= 1){
                s0 += __shfl_xor_sync(0xffffffffu, s0, msk);
                q0 += __shfl_xor_sync(0xffffffffu, q0, msk);
                mx0 = fmaxf(mx0, __shfl_xor_sync(0xffffffffu, mx0, msk));
                mn0 = fminf(mn0, __shfl_xor_sync(0xffffffffu, mn0, msk));
                s1 += __shfl_xor_sync(0xffffffffu, s1, msk);
                q1 += __shfl_xor_sync(0xffffffffu, q1, msk);
                mx1 = fmaxf(mx1, __shfl_xor_sync(0xffffffffu, mx1, msk));
                mn1 = fminf(mn1, __shfl_xor_sync(0xffffffffu, mn1, msk));
            }
            if (q == 0){
                int o0 = obase + 16*i + g;
                size_t ix0 = (size_t)bp*OO + o0;
                d_ps2s[ix0] = s0; d_ps2q[ix0] = q0; d_mx2[ix0] = mx0; d_mn2[ix0] = mn0;
                size_t ix1 = ix0 + 8;
                d_ps2s[ix1] = s1; d_ps2q[ix1] = q1; d_mx2[ix1] = mx1; d_mn2[ix1] = mn1;
            }
        }
    }
}

// ---------------- K5: BN2 + relu + max via monotonicity, transpose-write ----------------
__global__ void __launch_bounds__(256) k_final(float* __restrict__ out){
    int blk = blockIdx.x;                 // 256 blocks, 32 p's each
    int bp0 = blk * 32;
    int b = bp0 >> 11;
    int pbase = bp0 & 2047;
    int tid = threadIdx.x;
    __shared__ float sh[256*33];

    int o = tid;
    float sc = d_scale2[o], sf = d_shift2[o];
    for (int p = 0; p < 32; p++){
        size_t ix = (size_t)(bp0 + p)*OO + o;
        float mx = d_mx2[ix], mn = d_mn2[ix];
        float m = (sc >= 0.f) ? mx : mn;
        sh[o*33 + p] = fmaxf(fmaf(m, sc, sf), 0.f);
    }
    __syncthreads();

    int p   = tid & 31;
    int og0 = (tid >> 5) * 32;
    #pragma unroll
    for (int k = 0; k < 32; k++){
        int o2 = og0 + k;
        out[((size_t)(b*OO + o2))*Nn + pbase + p] = sh[o2*33 + p];
    }
}

// ---------------- launcher ----------------
extern "C" void kernel_launch(void* const* d_in, const int* in_sizes, int n_in,
                              void* d_out, int out_size){
    (void)in_sizes; (void)n_in; (void)out_size;
    const float* xyz  = (const float*)d_in[0];
    const float* feat = (const float*)d_in[1];
    const float* rot  = (const float*)d_in[2];
    const float* W1   = (const float*)d_in[3];
    const float* g1   = (const float*)d_in[4];
    const float* b1   = (const float*)d_in[5];
    const float* W2   = (const float*)d_in[6];
    const float* g2   = (const float*)d_in[7];
    const float* b2   = (const float*)d_in[8];
    float* out = (float*)d_out;

    cudaFuncSetAttribute(k_conv2, cudaFuncAttributeMaxDynamicSharedMemorySize, SMEMB);

    k_wt    <<<256, 256>>>(W1, W2);
    k_idx   <<<BP/8, 256>>>(xyz, rot);
    k_F1    <<<dim3(Nn/32, Bb), 256>>>(feat);
    k_stats1<<<BP, 128>>>(xyz, rot, W1);
    k_red_a <<<dim3(32,2), 256>>>(0);
    k_red_b <<<1, 256>>>(0, g1, b1);
    k_conv2 <<<BP/4, 512, SMEMB>>>(xyz, rot, W1);
    k_red_a <<<dim3(32,2), 256>>>(2);
    k_red_b <<<1, 256>>>(1, g2, b2);
    k_final <<<BP/32, 256>>>(out);
}

// round 9
// speedup vs baseline: 1.3503x; 1.0125x over previous
#include <cuda_runtime.h>
#include <cuda_fp16.h>
#include <cstdint>

#define Bb 4
#define Nn 2048
#define Cc 256
#define OO 256
#define Ss 32
#define BP (Bb*Nn)            // 8192
#define Ee (BP*Ss)            // 262144
#define K1 259

#define HMINf (-0.02f)
#define HMAXf (0.04f)
#define EPSf  (1e-5f)
#define INVCNT (1.0f/(float)Ee)
#define NSM 148

// ---------------- static device scratch (allocation-free rule) ----------------
__device__ float  d_W1fT[Cc*OO];            // W1fT[c][o] = W1[o][3+c]
__device__ __half d_W2h [OO*Cc];            // fp16 W2, k-slot-permuted: [o][p(c)]
__device__ int    d_idx [BP*Ss];            // neighbor indices
__device__ __half d_F1h [(size_t)Bb*Nn*OO]; // F1[b][n][o] fp16  (4MB, L2-resident)
__device__ float  d_ps1s[BP*OO], d_ps1q[BP*OO];   // stage-1 partial sums
__device__ float  d_ps2s[BP*OO], d_ps2q[BP*OO];   // stage-2 partial sums
__device__ float  d_mx2 [BP*OO], d_mn2 [BP*OO];   // per-(bp,o) max/min of y2 over s
__device__ float  d_pp  [4*32*OO];                // level-2 partials
__device__ float  d_scale1[OO], d_shift1[OO];
__device__ float  d_scale2[OO], d_shift2[OO];

// k-slot permutation: one thread's 4-half mma fragment = one contiguous 8B load.
// Pairs (2k, 2k+1) stay adjacent: kperm(c even) is even, kperm(c+1)=kperm(c)+1.
__device__ __forceinline__ int kperm(int c){
    int c16 = c & 15;
    int q  = (c16 & 7) >> 1;
    int r  = c16 & 1;
    int hi = (c16 >> 3) & 1;
    return (c & ~15) | (q*4 + hi*2 + r);
}

// ---------------- K0: weight prep ----------------
__global__ void k_wt(const float* __restrict__ W1, const float* __restrict__ W2){
    int i = blockIdx.x*256 + threadIdx.x;      // i = o*256 + c for W2
    int o = i >> 8, c = i & 255;
    d_W1fT[c*OO + o] = W1[o*K1 + 3 + c];
    d_W2h[o*Cc + kperm(c)] = __float2half_rn(W2[i]);
}

// ---------------- K1: cylinder query (one warp per (b,p)) ----------------
__global__ void k_idx(const float* __restrict__ xyz, const float* __restrict__ rot){
    int bp   = blockIdx.x*8 + (threadIdx.x >> 5);
    int lane = threadIdx.x & 31;
    int b = bp >> 11;
    const float* R = rot + (size_t)bp*9;
    float r00=R[0],r01=R[1],r02=R[2],r10=R[3],r11=R[4],r12=R[5],r20=R[6],r21=R[7],r22=R[8];
    const float* cc = xyz + (size_t)bp*3;
    float cx=cc[0], cy=cc[1], cz=cc[2];
    const float R2v = (float)(0.05*0.05);
    int count = 0, firstn = 0;
    bool have = false;
    for (int base = 0; base < Nn && count < Ss; base += 32){
        int n = base + lane;
        const float* q = xyz + ((size_t)b*Nn + n)*3;
        float dx=q[0]-cx, dy=q[1]-cy, dz=q[2]-cz;
        float a0 = r00*dx + r01*dy + r02*dz;
        float a1 = r10*dx + r11*dy + r12*dz;
        float a2 = r20*dx + r21*dy + r22*dz;
        bool m = (a1*a1 + a2*a2 < R2v) & (a0 > HMINf) & (a0 < HMAXf);
        unsigned bal = __ballot_sync(0xffffffffu, m);
        if (!have && bal){ firstn = base + (__ffs(bal) - 1); have = true; }
        int pre = __popc(bal & ((1u << lane) - 1u));
        if (m && count + pre < Ss) d_idx[bp*Ss + count + pre] = n;
        count += __popc(bal);
    }
    if (count < Ss){
        for (int j = count + lane; j < Ss; j += 32) d_idx[bp*Ss + j] = firstn;
    }
}

// ---------------- K2: F1 = W1_feat @ feat (fp32 compute, fp16 store) ----------------
__global__ void __launch_bounds__(256) k_F1(const float* __restrict__ feat){
    int b  = blockIdx.y;
    int n0 = blockIdx.x * 32;
    __shared__ __align__(16) float fsh[32][32];
    int tid = threadIdx.x;
    int o = tid;
    float acc[32];
    #pragma unroll
    for (int n = 0; n < 32; n++) acc[n] = 0.f;

    for (int ck = 0; ck < 8; ck++){
        #pragma unroll
        for (int r = 0; r < 4; r++){
            int li = tid + r*256;
            int ci = li >> 5, nj = li & 31;
            fsh[ci][nj] = feat[((size_t)b*Cc + ck*32 + ci)*Nn + n0 + nj];
        }
        __syncthreads();
        #pragma unroll 4
        for (int ci2 = 0; ci2 < 32; ci2++){
            float w = d_W1fT[(ck*32 + ci2)*OO + o];
            const float4* row = reinterpret_cast<const float4*>(&fsh[ci2][0]);
            #pragma unroll
            for (int nq = 0; nq < 8; nq++){
                float4 f = row[nq];
                acc[4*nq+0] = fmaf(f.x, w, acc[4*nq+0]);
                acc[4*nq+1] = fmaf(f.y, w, acc[4*nq+1]);
                acc[4*nq+2] = fmaf(f.z, w, acc[4*nq+2]);
                acc[4*nq+3] = fmaf(f.w, w, acc[4*nq+3]);
            }
        }
        __syncthreads();
    }
    #pragma unroll
    for (int n = 0; n < 32; n++)
        d_F1h[((size_t)b*Nn + n0 + n)*OO + o] = __float2half_rn(acc[n]);
}

// ---------------- K3: stats of conv1 output, half2 (128 threads = 2 o's each) ----------
__global__ void __launch_bounds__(128) k_stats1(const float* __restrict__ xyz,
                                                const float* __restrict__ rot,
                                                const float* __restrict__ W1){
    int bp = blockIdx.x;
    int b = bp >> 11;
    __shared__ int   idxs[32];
    __shared__ float gx[32], gy[32], gz[32];
    int tid = threadIdx.x;
    if (tid < 32){
        int s = tid;
        int i = d_idx[bp*Ss + s];
        idxs[s] = i;
        const float* R = rot + (size_t)bp*9;
        const float* c = xyz + (size_t)bp*3;
        const float* q = xyz + ((size_t)b*Nn + i)*3;
        float vx = (q[0]-c[0]) / 0.05f;
        float vy = (q[1]-c[1]) / 0.05f;
        float vz = (q[2]-c[2]) / 0.05f;
        gx[s] = vx*R[0] + vy*R[3] + vz*R[6];
        gy[s] = vx*R[1] + vy*R[4] + vz*R[7];
        gz[s] = vx*R[2] + vy*R[5] + vz*R[8];
    }
    __syncthreads();

    int c0 = tid*2;
    float wa0 = W1[c0*K1+0],     wa1 = W1[c0*K1+1],     wa2 = W1[c0*K1+2];
    float wb0 = W1[(c0+1)*K1+0], wb1 = W1[(c0+1)*K1+1], wb2 = W1[(c0+1)*K1+2];
    const __half2* F1b2 = (const __half2*)(d_F1h + (size_t)b*Nn*OO);
    float lsa = 0.f, lqa = 0.f, lsb = 0.f, lqb = 0.f;
    #pragma unroll 8
    for (int s = 0; s < Ss; s++){
        __half2 hv = F1b2[(size_t)idxs[s]*128 + tid];
        float2 f = __half22float2(hv);
        float va = fmaf(wa0, gx[s], fmaf(wa1, gy[s], fmaf(wa2, gz[s], f.x)));
        float vb = fmaf(wb0, gx[s], fmaf(wb1, gy[s], fmaf(wb2, gz[s], f.y)));
        lsa += va;  lqa = fmaf(va, va, lqa);
        lsb += vb;  lqb = fmaf(vb, vb, lqb);
    }
    d_ps1s[bp*OO + c0]     = lsa;  d_ps1q[bp*OO + c0]     = lqa;
    d_ps1s[bp*OO + c0 + 1] = lsb;  d_ps1q[bp*OO + c0 + 1] = lqb;
}

// ---------------- deterministic two-level reduction ----------------
__global__ void k_red_a(int base){
    int which = base + blockIdx.y;               // 0..3
    const float* src = (which == 0) ? d_ps1s : (which == 1) ? d_ps1q
                     : (which == 2) ? d_ps2s : d_ps2q;
    float* dst = d_pp + which*(32*OO);
    int z = blockIdx.x;                          // 0..31
    int o = threadIdx.x;
    float s = 0.f;
    for (int k = 0; k < 256; k++)
        s += src[((size_t)(z*256 + k))*OO + o];
    dst[z*OO + o] = s;
}

__global__ void k_red_b(int stage, const float* __restrict__ gamma,
                        const float* __restrict__ beta){
    int o = threadIdx.x;
    const float* pps = d_pp + (2*stage + 0)*(32*OO);
    const float* ppq = d_pp + (2*stage + 1)*(32*OO);
    float s = 0.f, q = 0.f;
    for (int z = 0; z < 32; z++){ s += pps[z*OO + o]; q += ppq[z*OO + o]; }
    float mu  = s * INVCNT;
    float var = q * INVCNT - mu*mu;
    float sc  = rsqrtf(var + EPSf) * gamma[o];
    float sf  = beta[o] - mu*sc;
    if (stage == 0){ d_scale1[o] = sc; d_shift1[o] = sf; }
    else           { d_scale2[o] = sc; d_shift2[o] = sf; }
}

// ---------------- fp16 mma helper ----------------
__device__ __forceinline__ void mma_f16(float& d0, float& d1, float& d2, float& d3,
                                        uint32_t a0, uint32_t a1, uint32_t a2, uint32_t a3,
                                        uint32_t b0, uint32_t b1){
    asm volatile("mma.sync.aligned.m16n8k16.row.col.f32.f16.f16.f32 "
                 "{%0,%1,%2,%3}, {%4,%5,%6,%7}, {%8,%9}, {%0,%1,%2,%3};\n"
                 : "+f"(d0), "+f"(d1), "+f"(d2), "+f"(d3)
                 : "r"(a0), "r"(a1), "r"(a2), "r"(a3), "r"(b0), "r"(b1));
}

#define HSTR 272   // halfs: 136 words == 8 (mod 32) -> conflict-free LDS.64 (both A and B)
// smem layout (bytes):
#define OFF_A   69632                 // h16: 128*HSTR*2 = 69632 before it
#define OFF_IDX 208896                // A: 256*HSTR*2 = 139264
#define OFF_GX  209408
#define OFF_GY  209920
#define OFF_GZ  210432
#define SMEMB   210944

// ---------------- K4: persistent conv2 — W2 resident in smem, loop over bp groups ----------
__global__ void __launch_bounds__(512, 1) k_conv2(const float* __restrict__ xyz,
                                                  const float* __restrict__ rot,
                                                  const float* __restrict__ W1){
    extern __shared__ __align__(16) char smraw[];
    __half* h16  = (__half*)smraw;                 // [128][HSTR]
    __half* Asm  = (__half*)(smraw + OFF_A);       // [256][HSTR]
    int*    idxs = (int*)(smraw + OFF_IDX);        // [128]
    float*  gxx  = (float*)(smraw + OFF_GX);
    float*  gyy  = (float*)(smraw + OFF_GY);
    float*  gzz  = (float*)(smraw + OFF_GZ);

    int tid = threadIdx.x;
    int lane = tid & 31, w = tid >> 5;
    int q = lane & 3, g = lane >> 2;
    int obase = (w & 7) * 32;                      // 8 warp-cols cover 256 o
    int warpS = (w >> 3) * 64;                     // 2 warp-rows cover 128 s

    // ---- load ALL of W2 into smem once (139264B = 8192 x 16B; 16 per thread) ----
    #pragma unroll
    for (int k = 0; k < 16; k++){
        int i = tid + k*512;                       // 0..8191
        int row = i >> 5, seg = i & 31;            // 256 rows x 32 segs
        uint32_t d = (uint32_t)__cvta_generic_to_shared(Asm + row*HSTR + seg*8);
        asm volatile("cp.async.cg.shared.global [%0], [%1], 16;\n"
                     :: "r"(d), "l"(d_W2h + (size_t)row*Cc + seg*8));
    }
    asm volatile("cp.async.commit_group;\n" ::: "memory");

    const char* Arow = (const char*)(Asm + (size_t)(obase + g)*HSTR);
    const char* Bsm  = (const char*)(h16 + (size_t)(warpS + g)*HSTR);

    for (int grp = blockIdx.x; grp < BP/4; grp += NSM){
        int bp0 = grp * 4;
        int b   = bp0 >> 11;

        // --- geometry for 4 bp's (128 samples) ---
        if (tid < 128){
            int s  = tid;
            int bp = bp0 + (s >> 5);
            int i  = d_idx[bp*Ss + (s & 31)];
            idxs[s] = i;
            const float* R = rot + (size_t)bp*9;
            const float* c = xyz + (size_t)bp*3;
            const float* pt = xyz + ((size_t)b*Nn + i)*3;
            float vx = (pt[0]-c[0]) / 0.05f;
            float vy = (pt[1]-c[1]) / 0.05f;
            float vz = (pt[2]-c[2]) / 0.05f;
            gxx[s] = vx*R[0] + vy*R[3] + vz*R[6];
            gyy[s] = vx*R[1] + vy*R[4] + vz*R[7];
            gzz[s] = vx*R[2] + vy*R[5] + vz*R[8];
        }
        __syncthreads();   // geom visible; also: all warps past last group's mma reads of h16

        // --- build h tile (half2: 2 channels per thread, 32 s each) ---
        {
            int cpair = tid & 127;
            int c0    = cpair*2;
            int sbase = (tid >> 7) * 32;
            int p     = kperm(c0);
            float wa0 = W1[c0*K1+0],     wa1 = W1[c0*K1+1],     wa2 = W1[c0*K1+2];
            float wb0 = W1[(c0+1)*K1+0], wb1 = W1[(c0+1)*K1+1], wb2 = W1[(c0+1)*K1+2];
            float sca = d_scale1[c0],   sfa = d_shift1[c0];
            float scb = d_scale1[c0+1], sfb = d_shift1[c0+1];
            const __half2* F1b2 = (const __half2*)(d_F1h + (size_t)b*Nn*OO);
            #pragma unroll 8
            for (int ds = 0; ds < 32; ds++){
                int s = sbase + ds;
                float2 f = __half22float2(F1b2[(size_t)idxs[s]*128 + cpair]);
                float va = fmaf(wa0, gxx[s], fmaf(wa1, gyy[s], fmaf(wa2, gzz[s], f.x)));
                float vb = fmaf(wb0, gxx[s], fmaf(wb1, gyy[s], fmaf(wb2, gzz[s], f.y)));
                va = fmaxf(fmaf(va, sca, sfa), 0.f);
                vb = fmaxf(fmaf(vb, scb, sfb), 0.f);
                *(__half2*)(h16 + s*HSTR + p) = __floats2half2_rn(va, vb);
            }
        }
        asm volatile("cp.async.wait_group 0;\n" ::: "memory");  // no-op after first group
        __syncthreads();

        // --- GEMM: D[o,s] = sum_c W2[o,c] * h[s,c], both operands in smem ---
        float acc[2][8][4];
        #pragma unroll
        for (int i = 0; i < 2; i++)
            #pragma unroll
            for (int j = 0; j < 8; j++)
                #pragma unroll
                for (int k = 0; k < 4; k++) acc[i][j][k] = 0.f;

        #pragma unroll 4
        for (int kt = 0; kt < 16; kt++){
            uint2 fa0 = *(const uint2*)(Arow +             0 + kt*32 + q*8);
            uint2 fa1 = *(const uint2*)(Arow +  8*HSTR*2      + kt*32 + q*8);
            uint2 fa2 = *(const uint2*)(Arow + 16*HSTR*2      + kt*32 + q*8);
            uint2 fa3 = *(const uint2*)(Arow + 24*HSTR*2      + kt*32 + q*8);
            #pragma unroll
            for (int j = 0; j < 8; j++){
                uint2 bv = *(const uint2*)(Bsm + j*(8*HSTR*2) + kt*32 + q*8);
                mma_f16(acc[0][j][0], acc[0][j][1], acc[0][j][2], acc[0][j][3],
                        fa0.x, fa1.x, fa0.y, fa1.y, bv.x, bv.y);
                mma_f16(acc[1][j][0], acc[1][j][1], acc[1][j][2], acc[1][j][3],
                        fa2.x, fa3.x, fa2.y, fa3.y, bv.x, bv.y);
            }
        }

        // --- epilogue: per-(bp,o) sum / sumsq / max / min over that bp's 32 s ---
        #pragma unroll
        for (int half = 0; half < 2; half++){
            int bp = bp0 + 2*(w >> 3) + half;
            #pragma unroll
            for (int i = 0; i < 2; i++){
                float s0=0.f, q0=0.f, mx0=-3.4e38f, mn0=3.4e38f;
                float s1=0.f, q1=0.f, mx1=-3.4e38f, mn1=3.4e38f;
                #pragma unroll
                for (int j4 = 0; j4 < 4; j4++){
                    const float* a = acc[i][half*4 + j4];
                    s0 += a[0] + a[1];
                    q0  = fmaf(a[0], a[0], fmaf(a[1], a[1], q0));
                    mx0 = fmaxf(mx0, fmaxf(a[0], a[1]));
                    mn0 = fminf(mn0, fminf(a[0], a[1]));
                    s1 += a[2] + a[3];
                    q1  = fmaf(a[2], a[2], fmaf(a[3], a[3], q1));
                    mx1 = fmaxf(mx1, fmaxf(a[2], a[3]));
                    mn1 = fminf(mn1, fminf(a[2], a[3]));
                }
                #pragma unroll
                for (int msk = 1; msk <= 2; msk <<= 1){
                    s0 += __shfl_xor_sync(0xffffffffu, s0, msk);
                    q0 += __shfl_xor_sync(0xffffffffu, q0, msk);
                    mx0 = fmaxf(mx0, __shfl_xor_sync(0xffffffffu, mx0, msk));
                    mn0 = fminf(mn0, __shfl_xor_sync(0xffffffffu, mn0, msk));
                    s1 += __shfl_xor_sync(0xffffffffu, s1, msk);
                    q1 += __shfl_xor_sync(0xffffffffu, q1, msk);
                    mx1 = fmaxf(mx1, __shfl_xor_sync(0xffffffffu, mx1, msk));
                    mn1 = fminf(mn1, __shfl_xor_sync(0xffffffffu, mn1, msk));
                }
                if (q == 0){
                    int o0 = obase + 16*i + g;
                    size_t ix0 = (size_t)bp*OO + o0;
                    d_ps2s[ix0] = s0; d_ps2q[ix0] = q0; d_mx2[ix0] = mx0; d_mn2[ix0] = mn0;
                    size_t ix1 = ix0 + 8;
                    d_ps2s[ix1] = s1; d_ps2q[ix1] = q1; d_mx2[ix1] = mx1; d_mn2[ix1] = mn1;
                }
            }
        }
    }
}

// ---------------- K5: BN2 + relu + max via monotonicity, transpose-write ----------------
__global__ void __launch_bounds__(256) k_final(float* __restrict__ out){
    int blk = blockIdx.x;                 // 256 blocks, 32 p's each
    int bp0 = blk * 32;
    int b = bp0 >> 11;
    int pbase = bp0 & 2047;
    int tid = threadIdx.x;
    __shared__ float sh[256*33];

    int o = tid;
    float sc = d_scale2[o], sf = d_shift2[o];
    for (int p = 0; p < 32; p++){
        size_t ix = (size_t)(bp0 + p)*OO + o;
        float mx = d_mx2[ix], mn = d_mn2[ix];
        float m = (sc >= 0.f) ? mx : mn;
        sh[o*33 + p] = fmaxf(fmaf(m, sc, sf), 0.f);
    }
    __syncthreads();

    int p   = tid & 31;
    int og0 = (tid >> 5) * 32;
    #pragma unroll
    for (int k = 0; k < 32; k++){
        int o2 = og0 + k;
        out[((size_t)(b*OO + o2))*Nn + pbase + p] = sh[o2*33 + p];
    }
}

// ---------------- launcher ----------------
extern "C" void kernel_launch(void* const* d_in, const int* in_sizes, int n_in,
                              void* d_out, int out_size){
    (void)in_sizes; (void)n_in; (void)out_size;
    const float* xyz  = (const float*)d_in[0];
    const float* feat = (const float*)d_in[1];
    const float* rot  = (const float*)d_in[2];
    const float* W1   = (const float*)d_in[3];
    const float* g1   = (const float*)d_in[4];
    const float* b1   = (const float*)d_in[5];
    const float* W2   = (const float*)d_in[6];
    const float* g2   = (const float*)d_in[7];
    const float* b2   = (const float*)d_in[8];
    float* out = (float*)d_out;

    cudaFuncSetAttribute(k_conv2, cudaFuncAttributeMaxDynamicSharedMemorySize, SMEMB);

    k_wt    <<<256, 256>>>(W1, W2);
    k_idx   <<<BP/8, 256>>>(xyz, rot);
    k_F1    <<<dim3(Nn/32, Bb), 256>>>(feat);
    k_stats1<<<BP, 128>>>(xyz, rot, W1);
    k_red_a <<<dim3(32,2), 256>>>(0);
    k_red_b <<<1, 256>>>(0, g1, b1);
    k_conv2 <<<NSM, 512, SMEMB>>>(xyz, rot, W1);
    k_red_a <<<dim3(32,2), 256>>>(2);
    k_red_b <<<1, 256>>>(1, g2, b2);
    k_final <<<BP/32, 256>>>(out);
}

// round 10
// speedup vs baseline: 1.4513x; 1.0748x over previous
#include <cuda_runtime.h>
#include <cuda_fp16.h>
#include <cstdint>

#define Bb 4
#define Nn 2048
#define Cc 256
#define OO 256
#define Ss 32
#define BP (Bb*Nn)            // 8192
#define Ee (BP*Ss)            // 262144
#define K1 259

#define HMINf (-0.02f)
#define HMAXf (0.04f)
#define EPSf  (1e-5f)
#define INVCNT (1.0f/(float)Ee)
#define NSM 148

// ---------------- static device scratch (allocation-free rule) ----------------
__device__ __half d_W2h [OO*Cc];            // fp16 W2, k-slot-permuted: [o][p(c)]
__device__ __half d_W1h [OO*Cc];            // fp16 W1 feature part, k-slot-permuted: [o][p(c)]
__device__ __half d_ftT [(size_t)Bb*Nn*Cc]; // feat transposed fp16: [b][n][p(c)]
__device__ int    d_idx [BP*Ss];            // neighbor indices
__device__ __half d_F1h [(size_t)Bb*Nn*OO]; // F1[b][n][o] fp16  (4MB, L2-resident)
__device__ float  d_ps1s[BP*OO], d_ps1q[BP*OO];   // stage-1 partial sums
__device__ float  d_ps2s[BP*OO], d_ps2q[BP*OO];   // stage-2 partial sums
__device__ float  d_mx2 [BP*OO], d_mn2 [BP*OO];   // per-(bp,o) max/min of y2 over s
__device__ float  d_pp  [4*32*OO];                // level-2 partials
__device__ float  d_scale1[OO], d_shift1[OO];
__device__ float  d_scale2[OO], d_shift2[OO];

// k-slot permutation: one thread's 4-half mma fragment = one contiguous 8B load.
// Pairs (2k, 2k+1) stay adjacent: kperm(c even) is even, kperm(c+1)=kperm(c)+1.
__device__ __forceinline__ int kperm(int c){
    int c16 = c & 15;
    int q  = (c16 & 7) >> 1;
    int r  = c16 & 1;
    int hi = (c16 >> 3) & 1;
    return (c & ~15) | (q*4 + hi*2 + r);
}

// ---------------- K0: weight prep ----------------
__global__ void k_wt(const float* __restrict__ W1, const float* __restrict__ W2){
    int i = blockIdx.x*256 + threadIdx.x;      // i = o*256 + c
    int o = i >> 8, c = i & 255;
    d_W1h[o*Cc + kperm(c)] = __float2half_rn(W1[o*K1 + 3 + c]);
    d_W2h[o*Cc + kperm(c)] = __float2half_rn(W2[i]);
}

// ---------------- K0b: transpose feat [b][c][n] -> fp16 [b][n][kperm(c)] ----------------
__global__ void __launch_bounds__(256) k_tr(const float* __restrict__ feat){
    int blk = blockIdx.x;                 // b(4) x ct(8) x nt(64)
    int b  = blk >> 9;
    int ct = (blk >> 6) & 7;
    int nt = blk & 63;
    int n0 = nt*32, c0 = ct*32;
    __shared__ float tsh[32][33];
    int t = threadIdx.x;
    // read: 8 c-rows per... t -> c-row (t>>3), n-quad ((t&7)*4)
    {
        int cr = t >> 3, nq = (t & 7)*4;
        const float4 v = *(const float4*)(feat + ((size_t)b*Cc + c0 + cr)*Nn + n0 + nq);
        tsh[cr][nq+0] = v.x; tsh[cr][nq+1] = v.y; tsh[cr][nq+2] = v.z; tsh[cr][nq+3] = v.w;
        cr += 32; // second half handled below
    }
    {
        int cr = (t >> 3) + 0; (void)cr;
    }
    __syncthreads();
    // write: t -> n-row (t>>3), 4 c's ((t&7)*4); kperm pairs stay adjacent
    {
        int n = t >> 3, cl = (t & 7)*4;
        __half* dst = d_ftT + ((size_t)b*Nn + n0 + n)*Cc;
        #pragma unroll
        for (int w = 0; w < 2; w++){
            int cg = c0 + cl + w*2;            // even
            __half2 hv = __floats2half2_rn(tsh[cl + w*2][n], tsh[cl + w*2 + 1][n]);
            *(__half2*)(dst + kperm(cg)) = hv;
        }
    }
}

// ---------------- K1: cylinder query (one warp per (b,p)) ----------------
__global__ void k_idx(const float* __restrict__ xyz, const float* __restrict__ rot){
    int bp   = blockIdx.x*8 + (threadIdx.x >> 5);
    int lane = threadIdx.x & 31;
    int b = bp >> 11;
    const float* R = rot + (size_t)bp*9;
    float r00=R[0],r01=R[1],r02=R[2],r10=R[3],r11=R[4],r12=R[5],r20=R[6],r21=R[7],r22=R[8];
    const float* cc = xyz + (size_t)bp*3;
    float cx=cc[0], cy=cc[1], cz=cc[2];
    const float R2v = (float)(0.05*0.05);
    int count = 0, firstn = 0;
    bool have = false;
    for (int base = 0; base < Nn && count < Ss; base += 32){
        int n = base + lane;
        const float* q = xyz + ((size_t)b*Nn + n)*3;
        float dx=q[0]-cx, dy=q[1]-cy, dz=q[2]-cz;
        float a0 = r00*dx + r01*dy + r02*dz;
        float a1 = r10*dx + r11*dy + r12*dz;
        float a2 = r20*dx + r21*dy + r22*dz;
        bool m = (a1*a1 + a2*a2 < R2v) & (a0 > HMINf) & (a0 < HMAXf);
        unsigned bal = __ballot_sync(0xffffffffu, m);
        if (!have && bal){ firstn = base + (__ffs(bal) - 1); have = true; }
        int pre = __popc(bal & ((1u << lane) - 1u));
        if (m && count + pre < Ss) d_idx[bp*Ss + count + pre] = n;
        count += __popc(bal);
    }
    if (count < Ss){
        for (int j = count + lane; j < Ss; j += 32) d_idx[bp*Ss + j] = firstn;
    }
}

// ---------------- fp16 mma helper ----------------
__device__ __forceinline__ void mma_f16(float& d0, float& d1, float& d2, float& d3,
                                        uint32_t a0, uint32_t a1, uint32_t a2, uint32_t a3,
                                        uint32_t b0, uint32_t b1){
    asm volatile("mma.sync.aligned.m16n8k16.row.col.f32.f16.f16.f32 "
                 "{%0,%1,%2,%3}, {%4,%5,%6,%7}, {%8,%9}, {%0,%1,%2,%3};\n"
                 : "+f"(d0), "+f"(d1), "+f"(d2), "+f"(d3)
                 : "r"(a0), "r"(a1), "r"(a2), "r"(a3), "r"(b0), "r"(b1));
}

#define HSTR 272   // halfs: 136 words == 8 (mod 32) -> conflict-free LDS.64 frags

// ---------------- K2: F1 on tensor cores ----------------
// F1[n][o] = sum_c ftT[n][c] * W1h[o][c].  M=n(64/block), N=o(256), K=c(256).
// smem: M-tile ftT [64][HSTR] @0 (34816B), N-op W1h [256][HSTR] @34816 (139264B)
#define F1_SMEM (34816 + 139264)
__global__ void __launch_bounds__(256) k_F1mma(){
    extern __shared__ __align__(16) char sm1[];
    __half* Mt = (__half*)sm1;                   // ftT tile [64][HSTR]
    __half* Nw = (__half*)(sm1 + 34816);         // W1h [256][HSTR]
    int tid = threadIdx.x;
    int blk = blockIdx.x;                        // 128 = b(4) x nt(32)
    int b  = blk >> 5;
    int n0 = (blk & 31) * 64;

    // cp.async: W1h 256 rows x 32 segs(16B); ftT tile 64 rows x 32 segs
    #pragma unroll
    for (int k = 0; k < 32; k++){
        int i = tid + k*256;                     // 0..8191
        int row = i >> 5, seg = i & 31;
        uint32_t d = (uint32_t)__cvta_generic_to_shared(Nw + row*HSTR + seg*8);
        asm volatile("cp.async.cg.shared.global [%0], [%1], 16;\n"
                     :: "r"(d), "l"(d_W1h + (size_t)row*Cc + seg*8));
    }
    #pragma unroll
    for (int k = 0; k < 8; k++){
        int i = tid + k*256;                     // 0..2047
        int row = i >> 5, seg = i & 31;
        uint32_t d = (uint32_t)__cvta_generic_to_shared(Mt + row*HSTR + seg*8);
        asm volatile("cp.async.cg.shared.global [%0], [%1], 16;\n"
                     :: "r"(d), "l"(d_ftT + ((size_t)b*Nn + n0 + row)*Cc + seg*8));
    }
    asm volatile("cp.async.commit_group;\n" ::: "memory");
    asm volatile("cp.async.wait_group 0;\n" ::: "memory");
    __syncthreads();

    int lane = tid & 31, w = tid >> 5;
    int q = lane & 3, g = lane >> 2;
    int obase = w * 32;                          // 8 warps x 32 o

    float acc[4][4][4];
    #pragma unroll
    for (int mt = 0; mt < 4; mt++)
        #pragma unroll
        for (int ot = 0; ot < 4; ot++)
            #pragma unroll
            for (int k = 0; k < 4; k++) acc[mt][ot][k] = 0.f;

    const char* Mrow = (const char*)(Mt + (size_t)g*HSTR);
    const char* Nrow = (const char*)(Nw + (size_t)(obase + g)*HSTR);

    #pragma unroll 4
    for (int kt = 0; kt < 16; kt++){
        int ko = kt*32 + q*8;
        uint2 ma[4][2];
        #pragma unroll
        for (int mt = 0; mt < 4; mt++){
            ma[mt][0] = *(const uint2*)(Mrow + (mt*16    )*HSTR*2 + ko);
            ma[mt][1] = *(const uint2*)(Mrow + (mt*16 + 8)*HSTR*2 + ko);
        }
        #pragma unroll
        for (int ot = 0; ot < 4; ot++){
            uint2 nb = *(const uint2*)(Nrow + (ot*8)*HSTR*2 + ko);
            #pragma unroll
            for (int mt = 0; mt < 4; mt++){
                mma_f16(acc[mt][ot][0], acc[mt][ot][1], acc[mt][ot][2], acc[mt][ot][3],
                        ma[mt][0].x, ma[mt][1].x, ma[mt][0].y, ma[mt][1].y, nb.x, nb.y);
            }
        }
    }

    // store F1h[n][o] as half2 (o = obase + ot*8 + 2q, even)
    #pragma unroll
    for (int mt = 0; mt < 4; mt++){
        #pragma unroll
        for (int ot = 0; ot < 4; ot++){
            int o = obase + ot*8 + 2*q;
            int n = n0 + mt*16 + g;
            __half* dst = d_F1h + ((size_t)b*Nn + n)*OO + o;
            *(__half2*)dst = __floats2half2_rn(acc[mt][ot][0], acc[mt][ot][1]);
            *(__half2*)(dst + 8*OO) = __floats2half2_rn(acc[mt][ot][2], acc[mt][ot][3]);
        }
    }
}

// ---------------- K3: stats of conv1 output, 2 bp per 256-thread block ----------------
__global__ void __launch_bounds__(256) k_stats1(const float* __restrict__ xyz,
                                                const float* __restrict__ rot,
                                                const float* __restrict__ W1){
    int sub = threadIdx.x >> 7;           // 0/1
    int t   = threadIdx.x & 127;
    int bp  = blockIdx.x*2 + sub;
    int b = bp >> 11;
    __shared__ int   idxs[2][32];
    __shared__ float gx[2][32], gy[2][32], gz[2][32];
    if (t < 32){
        int s = t;
        int i = d_idx[bp*Ss + s];
        idxs[sub][s] = i;
        const float* R = rot + (size_t)bp*9;
        const float* c = xyz + (size_t)bp*3;
        const float* q = xyz + ((size_t)b*Nn + i)*3;
        float vx = (q[0]-c[0]) / 0.05f;
        float vy = (q[1]-c[1]) / 0.05f;
        float vz = (q[2]-c[2]) / 0.05f;
        gx[sub][s] = vx*R[0] + vy*R[3] + vz*R[6];
        gy[sub][s] = vx*R[1] + vy*R[4] + vz*R[7];
        gz[sub][s] = vx*R[2] + vy*R[5] + vz*R[8];
    }
    __syncthreads();

    int c0 = t*2;
    float wa0 = W1[c0*K1+0],     wa1 = W1[c0*K1+1],     wa2 = W1[c0*K1+2];
    float wb0 = W1[(c0+1)*K1+0], wb1 = W1[(c0+1)*K1+1], wb2 = W1[(c0+1)*K1+2];
    const __half2* F1b2 = (const __half2*)(d_F1h + (size_t)b*Nn*OO);
    float lsa = 0.f, lqa = 0.f, lsb = 0.f, lqb = 0.f;
    #pragma unroll 8
    for (int s = 0; s < Ss; s++){
        __half2 hv = F1b2[(size_t)idxs[sub][s]*128 + t];
        float2 f = __half22float2(hv);
        float va = fmaf(wa0, gx[sub][s], fmaf(wa1, gy[sub][s], fmaf(wa2, gz[sub][s], f.x)));
        float vb = fmaf(wb0, gx[sub][s], fmaf(wb1, gy[sub][s], fmaf(wb2, gz[sub][s], f.y)));
        lsa += va;  lqa = fmaf(va, va, lqa);
        lsb += vb;  lqb = fmaf(vb, vb, lqb);
    }
    d_ps1s[bp*OO + c0]     = lsa;  d_ps1q[bp*OO + c0]     = lqa;
    d_ps1s[bp*OO + c0 + 1] = lsb;  d_ps1q[bp*OO + c0 + 1] = lqb;
}

// ---------------- deterministic two-level reduction ----------------
__global__ void k_red_a(int base){
    int which = base + blockIdx.y;               // 0..3
    const float* src = (which == 0) ? d_ps1s : (which == 1) ? d_ps1q
                     : (which == 2) ? d_ps2s : d_ps2q;
    float* dst = d_pp + which*(32*OO);
    int z = blockIdx.x;                          // 0..31
    int o = threadIdx.x;
    float s = 0.f;
    for (int k = 0; k < 256; k++)
        s += src[((size_t)(z*256 + k))*OO + o];
    dst[z*OO + o] = s;
}

__global__ void k_red_b(int stage, const float* __restrict__ gamma,
                        const float* __restrict__ beta){
    int o = threadIdx.x;
    const float* pps = d_pp + (2*stage + 0)*(32*OO);
    const float* ppq = d_pp + (2*stage + 1)*(32*OO);
    float s = 0.f, q = 0.f;
    for (int z = 0; z < 32; z++){ s += pps[z*OO + o]; q += ppq[z*OO + o]; }
    float mu  = s * INVCNT;
    float var = q * INVCNT - mu*mu;
    float sc  = rsqrtf(var + EPSf) * gamma[o];
    float sf  = beta[o] - mu*sc;
    if (stage == 0){ d_scale1[o] = sc; d_shift1[o] = sf; }
    else           { d_scale2[o] = sc; d_shift2[o] = sf; }
}

// smem layout (bytes) for conv2:
#define OFF_A   69632                 // h16: 128*HSTR*2 = 69632 before it
#define OFF_IDX 208896                // A: 256*HSTR*2 = 139264
#define OFF_GX  209408
#define OFF_GY  209920
#define OFF_GZ  210432
#define SMEMB   210944

// ---------------- K4: persistent conv2 — W2 resident in smem, loop over bp groups ----------
__global__ void __launch_bounds__(512, 1) k_conv2(const float* __restrict__ xyz,
                                                  const float* __restrict__ rot,
                                                  const float* __restrict__ W1){
    extern __shared__ __align__(16) char smraw[];
    __half* h16  = (__half*)smraw;                 // [128][HSTR]
    __half* Asm  = (__half*)(smraw + OFF_A);       // [256][HSTR]
    int*    idxs = (int*)(smraw + OFF_IDX);        // [128]
    float*  gxx  = (float*)(smraw + OFF_GX);
    float*  gyy  = (float*)(smraw + OFF_GY);
    float*  gzz  = (float*)(smraw + OFF_GZ);

    int tid = threadIdx.x;
    int lane = tid & 31, w = tid >> 5;
    int q = lane & 3, g = lane >> 2;
    int obase = (w & 7) * 32;                      // 8 warp-cols cover 256 o
    int warpS = (w >> 3) * 64;                     // 2 warp-rows cover 128 s

    // ---- load ALL of W2 into smem once ----
    #pragma unroll
    for (int k = 0; k < 16; k++){
        int i = tid + k*512;                       // 0..8191
        int row = i >> 5, seg = i & 31;
        uint32_t d = (uint32_t)__cvta_generic_to_shared(Asm + row*HSTR + seg*8);
        asm volatile("cp.async.cg.shared.global [%0], [%1], 16;\n"
                     :: "r"(d), "l"(d_W2h + (size_t)row*Cc + seg*8));
    }
    asm volatile("cp.async.commit_group;\n" ::: "memory");

    const char* Arow = (const char*)(Asm + (size_t)(obase + g)*HSTR);
    const char* Bsm  = (const char*)(h16 + (size_t)(warpS + g)*HSTR);

    for (int grp = blockIdx.x; grp < BP/4; grp += NSM){
        int bp0 = grp * 4;
        int b   = bp0 >> 11;

        if (tid < 128){
            int s  = tid;
            int bp = bp0 + (s >> 5);
            int i  = d_idx[bp*Ss + (s & 31)];
            idxs[s] = i;
            const float* R = rot + (size_t)bp*9;
            const float* c = xyz + (size_t)bp*3;
            const float* pt = xyz + ((size_t)b*Nn + i)*3;
            float vx = (pt[0]-c[0]) / 0.05f;
            float vy = (pt[1]-c[1]) / 0.05f;
            float vz = (pt[2]-c[2]) / 0.05f;
            gxx[s] = vx*R[0] + vy*R[3] + vz*R[6];
            gyy[s] = vx*R[1] + vy*R[4] + vz*R[7];
            gzz[s] = vx*R[2] + vy*R[5] + vz*R[8];
        }
        __syncthreads();

        {
            int cpair = tid & 127;
            int c0    = cpair*2;
            int sbase = (tid >> 7) * 32;
            int p     = kperm(c0);
            float wa0 = W1[c0*K1+0],     wa1 = W1[c0*K1+1],     wa2 = W1[c0*K1+2];
            float wb0 = W1[(c0+1)*K1+0], wb1 = W1[(c0+1)*K1+1], wb2 = W1[(c0+1)*K1+2];
            float sca = d_scale1[c0],   sfa = d_shift1[c0];
            float scb = d_scale1[c0+1], sfb = d_shift1[c0+1];
            const __half2* F1b2 = (const __half2*)(d_F1h + (size_t)b*Nn*OO);
            #pragma unroll 8
            for (int ds = 0; ds < 32; ds++){
                int s = sbase + ds;
                float2 f = __half22float2(F1b2[(size_t)idxs[s]*128 + cpair]);
                float va = fmaf(wa0, gxx[s], fmaf(wa1, gyy[s], fmaf(wa2, gzz[s], f.x)));
                float vb = fmaf(wb0, gxx[s], fmaf(wb1, gyy[s], fmaf(wb2, gzz[s], f.y)));
                va = fmaxf(fmaf(va, sca, sfa), 0.f);
                vb = fmaxf(fmaf(vb, scb, sfb), 0.f);
                *(__half2*)(h16 + s*HSTR + p) = __floats2half2_rn(va, vb);
            }
        }
        asm volatile("cp.async.wait_group 0;\n" ::: "memory");
        __syncthreads();

        float acc[2][8][4];
        #pragma unroll
        for (int i = 0; i < 2; i++)
            #pragma unroll
            for (int j = 0; j < 8; j++)
                #pragma unroll
                for (int k = 0; k < 4; k++) acc[i][j][k] = 0.f;

        #pragma unroll 4
        for (int kt = 0; kt < 16; kt++){
            uint2 fa0 = *(const uint2*)(Arow +             0 + kt*32 + q*8);
            uint2 fa1 = *(const uint2*)(Arow +  8*HSTR*2      + kt*32 + q*8);
            uint2 fa2 = *(const uint2*)(Arow + 16*HSTR*2      + kt*32 + q*8);
            uint2 fa3 = *(const uint2*)(Arow + 24*HSTR*2      + kt*32 + q*8);
            #pragma unroll
            for (int j = 0; j < 8; j++){
                uint2 bv = *(const uint2*)(Bsm + j*(8*HSTR*2) + kt*32 + q*8);
                mma_f16(acc[0][j][0], acc[0][j][1], acc[0][j][2], acc[0][j][3],
                        fa0.x, fa1.x, fa0.y, fa1.y, bv.x, bv.y);
                mma_f16(acc[1][j][0], acc[1][j][1], acc[1][j][2], acc[1][j][3],
                        fa2.x, fa3.x, fa2.y, fa3.y, bv.x, bv.y);
            }
        }

        #pragma unroll
        for (int half = 0; half < 2; half++){
            int bp = bp0 + 2*(w >> 3) + half;
            #pragma unroll
            for (int i = 0; i < 2; i++){
                float s0=0.f, q0=0.f, mx0=-3.4e38f, mn0=3.4e38f;
                float s1=0.f, q1=0.f, mx1=-3.4e38f, mn1=3.4e38f;
                #pragma unroll
                for (int j4 = 0; j4 < 4; j4++){
                    const float* a = acc[i][half*4 + j4];
                    s0 += a[0] + a[1];
                    q0  = fmaf(a[0], a[0], fmaf(a[1], a[1], q0));
                    mx0 = fmaxf(mx0, fmaxf(a[0], a[1]));
                    mn0 = fminf(mn0, fminf(a[0], a[1]));
                    s1 += a[2] + a[3];
                    q1  = fmaf(a[2], a[2], fmaf(a[3], a[3], q1));
                    mx1 = fmaxf(mx1, fmaxf(a[2], a[3]));
                    mn1 = fminf(mn1, fminf(a[2], a[3]));
                }
                #pragma unroll
                for (int msk = 1; msk <= 2; msk <<= 1){
                    s0 += __shfl_xor_sync(0xffffffffu, s0, msk);
                    q0 += __shfl_xor_sync(0xffffffffu, q0, msk);
                    mx0 = fmaxf(mx0, __shfl_xor_sync(0xffffffffu, mx0, msk));
                    mn0 = fminf(mn0, __shfl_xor_sync(0xffffffffu, mn0, msk));
                    s1 += __shfl_xor_sync(0xffffffffu, s1, msk);
                    q1 += __shfl_xor_sync(0xffffffffu, q1, msk);
                    mx1 = fmaxf(mx1, __shfl_xor_sync(0xffffffffu, mx1, msk));
                    mn1 = fminf(mn1, __shfl_xor_sync(0xffffffffu, mn1, msk));
                }
                if (q == 0){
                    int o0 = obase + 16*i + g;
                    size_t ix0 = (size_t)bp*OO + o0;
                    d_ps2s[ix0] = s0; d_ps2q[ix0] = q0; d_mx2[ix0] = mx0; d_mn2[ix0] = mn0;
                    size_t ix1 = ix0 + 8;
                    d_ps2s[ix1] = s1; d_ps2q[ix1] = q1; d_mx2[ix1] = mx1; d_mn2[ix1] = mn1;
                }
            }
        }
    }
}

// ---------------- K5: BN2 + relu + max via monotonicity, transpose-write ----------------
__global__ void __launch_bounds__(256) k_final(float* __restrict__ out){
    int blk = blockIdx.x;                 // 256 blocks, 32 p's each
    int bp0 = blk * 32;
    int b = bp0 >> 11;
    int pbase = bp0 & 2047;
    int tid = threadIdx.x;
    __shared__ float sh[256*33];

    int o = tid;
    float sc = d_scale2[o], sf = d_shift2[o];
    for (int p = 0; p < 32; p++){
        size_t ix = (size_t)(bp0 + p)*OO + o;
        float mx = d_mx2[ix], mn = d_mn2[ix];
        float m = (sc >= 0.f) ? mx : mn;
        sh[o*33 + p] = fmaxf(fmaf(m, sc, sf), 0.f);
    }
    __syncthreads();

    int p   = tid & 31;
    int og0 = (tid >> 5) * 32;
    #pragma unroll
    for (int k = 0; k < 32; k++){
        int o2 = og0 + k;
        out[((size_t)(b*OO + o2))*Nn + pbase + p] = sh[o2*33 + p];
    }
}

// ---------------- launcher ----------------
extern "C" void kernel_launch(void* const* d_in, const int* in_sizes, int n_in,
                              void* d_out, int out_size){
    (void)in_sizes; (void)n_in; (void)out_size;
    const float* xyz  = (const float*)d_in[0];
    const float* feat = (const float*)d_in[1];
    const float* rot  = (const float*)d_in[2];
    const float* W1   = (const float*)d_in[3];
    const float* g1   = (const float*)d_in[4];
    const float* b1   = (const float*)d_in[5];
    const float* W2   = (const float*)d_in[6];
    const float* g2   = (const float*)d_in[7];
    const float* b2   = (const float*)d_in[8];
    float* out = (float*)d_out;

    cudaFuncSetAttribute(k_conv2, cudaFuncAttributeMaxDynamicSharedMemorySize, SMEMB);
    cudaFuncSetAttribute(k_F1mma, cudaFuncAttributeMaxDynamicSharedMemorySize, F1_SMEM);

    k_wt    <<<256, 256>>>(W1, W2);
    k_tr    <<<2048, 256>>>(feat);
    k_idx   <<<BP/8, 256>>>(xyz, rot);
    k_F1mma <<<128, 256, F1_SMEM>>>();
    k_stats1<<<BP/2, 256>>>(xyz, rot, W1);
    k_red_a <<<dim3(32,2), 256>>>(0);
    k_red_b <<<1, 256>>>(0, g1, b1);
    k_conv2 <<<NSM, 512, SMEMB>>>(xyz, rot, W1);
    k_red_a <<<dim3(32,2), 256>>>(2);
    k_red_b <<<1, 256>>>(1, g2, b2);
    k_final <<<BP/32, 256>>>(out);
}

// round 11
// speedup vs baseline: 1.5247x; 1.0506x over previous
#include <cuda_runtime.h>
#include <cuda_fp16.h>
#include <cstdint>

#define Bb 4
#define Nn 2048
#define Cc 256
#define OO 256
#define Ss 32
#define BP (Bb*Nn)            // 8192
#define Ee (BP*Ss)            // 262144
#define K1 259

#define HMINf (-0.02f)
#define HMAXf (0.04f)
#define EPSf  (1e-5f)
#define INVCNT (1.0f/(float)Ee)
#define NSM 148

// ---------------- static device scratch (allocation-free rule) ----------------
__device__ __half d_W2h [OO*Cc];            // fp16 W2, k-slot-permuted: [o][p(c)]
__device__ __half d_W1h [OO*Cc];            // fp16 W1 feature part, k-slot-permuted: [o][p(c)]
__device__ __half d_ftT [(size_t)Bb*Nn*Cc]; // feat transposed fp16: [b][n][p(c)]
__device__ int    d_idx [BP*Ss];            // neighbor indices
__device__ __half d_F1h [(size_t)Bb*Nn*OO]; // F1[b][n][o] fp16  (4MB, L2-resident)
__device__ float  d_ps1s[BP*OO], d_ps1q[BP*OO];   // stage-1 partial sums
__device__ float  d_ps2s[BP*OO], d_ps2q[BP*OO];   // stage-2 partial sums
__device__ float  d_mx2 [BP*OO], d_mn2 [BP*OO];   // per-(bp,o) max/min of y2 over s
__device__ float  d_pp  [4*32*OO];                // level-2 partials
__device__ float  d_scale2[OO], d_shift2[OO];

// k-slot permutation: one thread's 4-half mma fragment = one contiguous 8B load.
__device__ __forceinline__ int kperm(int c){
    int c16 = c & 15;
    int q  = (c16 & 7) >> 1;
    int r  = c16 & 1;
    int hi = (c16 >> 3) & 1;
    return (c & ~15) | (q*4 + hi*2 + r);
}

// ---------------- K0: fused weight prep + feat transpose ----------------
__global__ void __launch_bounds__(256) k_wtr(const float* __restrict__ W1,
                                             const float* __restrict__ W2,
                                             const float* __restrict__ feat){
    if (blockIdx.x < 256){
        int i = blockIdx.x*256 + threadIdx.x;      // i = o*256 + c
        int o = i >> 8, c = i & 255;
        d_W1h[o*Cc + kperm(c)] = __float2half_rn(W1[o*K1 + 3 + c]);
        d_W2h[o*Cc + kperm(c)] = __float2half_rn(W2[i]);
        return;
    }
    int blk = blockIdx.x - 256;           // b(4) x ct(8) x nt(64)
    int b  = blk >> 9;
    int ct = (blk >> 6) & 7;
    int nt = blk & 63;
    int n0 = nt*32, c0 = ct*32;
    __shared__ float tsh[32][33];
    int t = threadIdx.x;
    {
        int cr = t >> 3, nq = (t & 7)*4;
        const float4 v = *(const float4*)(feat + ((size_t)b*Cc + c0 + cr)*Nn + n0 + nq);
        tsh[cr][nq+0] = v.x; tsh[cr][nq+1] = v.y; tsh[cr][nq+2] = v.z; tsh[cr][nq+3] = v.w;
    }
    __syncthreads();
    {
        int n = t >> 3, cl = (t & 7)*4;
        __half* dst = d_ftT + ((size_t)b*Nn + n0 + n)*Cc;
        #pragma unroll
        for (int w = 0; w < 2; w++){
            int cg = c0 + cl + w*2;            // even
            __half2 hv = __floats2half2_rn(tsh[cl + w*2][n], tsh[cl + w*2 + 1][n]);
            *(__half2*)(dst + kperm(cg)) = hv;
        }
    }
}

// ---------------- K1: cylinder query (one warp per (b,p)) ----------------
__global__ void k_idx(const float* __restrict__ xyz, const float* __restrict__ rot){
    int bp   = blockIdx.x*8 + (threadIdx.x >> 5);
    int lane = threadIdx.x & 31;
    int b = bp >> 11;
    const float* R = rot + (size_t)bp*9;
    float r00=R[0],r01=R[1],r02=R[2],r10=R[3],r11=R[4],r12=R[5],r20=R[6],r21=R[7],r22=R[8];
    const float* cc = xyz + (size_t)bp*3;
    float cx=cc[0], cy=cc[1], cz=cc[2];
    const float R2v = (float)(0.05*0.05);
    int count = 0, firstn = 0;
    bool have = false;
    for (int base = 0; base < Nn && count < Ss; base += 32){
        int n = base + lane;
        const float* q = xyz + ((size_t)b*Nn + n)*3;
        float dx=q[0]-cx, dy=q[1]-cy, dz=q[2]-cz;
        float a0 = r00*dx + r01*dy + r02*dz;
        float a1 = r10*dx + r11*dy + r12*dz;
        float a2 = r20*dx + r21*dy + r22*dz;
        bool m = (a1*a1 + a2*a2 < R2v) & (a0 > HMINf) & (a0 < HMAXf);
        unsigned bal = __ballot_sync(0xffffffffu, m);
        if (!have && bal){ firstn = base + (__ffs(bal) - 1); have = true; }
        int pre = __popc(bal & ((1u << lane) - 1u));
        if (m && count + pre < Ss) d_idx[bp*Ss + count + pre] = n;
        count += __popc(bal);
    }
    if (count < Ss){
        for (int j = count + lane; j < Ss; j += 32) d_idx[bp*Ss + j] = firstn;
    }
}

// ---------------- fp16 mma helper ----------------
__device__ __forceinline__ void mma_f16(float& d0, float& d1, float& d2, float& d3,
                                        uint32_t a0, uint32_t a1, uint32_t a2, uint32_t a3,
                                        uint32_t b0, uint32_t b1){
    asm volatile("mma.sync.aligned.m16n8k16.row.col.f32.f16.f16.f32 "
                 "{%0,%1,%2,%3}, {%4,%5,%6,%7}, {%8,%9}, {%0,%1,%2,%3};\n"
                 : "+f"(d0), "+f"(d1), "+f"(d2), "+f"(d3)
                 : "r"(a0), "r"(a1), "r"(a2), "r"(a3), "r"(b0), "r"(b1));
}

#define HSTR 272   // halfs: 136 words == 8 (mod 32) -> conflict-free LDS.64 frags

// ---------------- K2: F1 on tensor cores ----------------
#define F1_SMEM (34816 + 139264)
__global__ void __launch_bounds__(256) k_F1mma(){
    extern __shared__ __align__(16) char sm1[];
    __half* Mt = (__half*)sm1;                   // ftT tile [64][HSTR]
    __half* Nw = (__half*)(sm1 + 34816);         // W1h [256][HSTR]
    int tid = threadIdx.x;
    int blk = blockIdx.x;                        // 128 = b(4) x nt(32)
    int b  = blk >> 5;
    int n0 = (blk & 31) * 64;

    #pragma unroll
    for (int k = 0; k < 32; k++){
        int i = tid + k*256;
        int row = i >> 5, seg = i & 31;
        uint32_t d = (uint32_t)__cvta_generic_to_shared(Nw + row*HSTR + seg*8);
        asm volatile("cp.async.cg.shared.global [%0], [%1], 16;\n"
                     :: "r"(d), "l"(d_W1h + (size_t)row*Cc + seg*8));
    }
    #pragma unroll
    for (int k = 0; k < 8; k++){
        int i = tid + k*256;
        int row = i >> 5, seg = i & 31;
        uint32_t d = (uint32_t)__cvta_generic_to_shared(Mt + row*HSTR + seg*8);
        asm volatile("cp.async.cg.shared.global [%0], [%1], 16;\n"
                     :: "r"(d), "l"(d_ftT + ((size_t)b*Nn + n0 + row)*Cc + seg*8));
    }
    asm volatile("cp.async.commit_group;\n" ::: "memory");
    asm volatile("cp.async.wait_group 0;\n" ::: "memory");
    __syncthreads();

    int lane = tid & 31, w = tid >> 5;
    int q = lane & 3, g = lane >> 2;
    int obase = w * 32;

    float acc[4][4][4];
    #pragma unroll
    for (int mt = 0; mt < 4; mt++)
        #pragma unroll
        for (int ot = 0; ot < 4; ot++)
            #pragma unroll
            for (int k = 0; k < 4; k++) acc[mt][ot][k] = 0.f;

    const char* Mrow = (const char*)(Mt + (size_t)g*HSTR);
    const char* Nrow = (const char*)(Nw + (size_t)(obase + g)*HSTR);

    #pragma unroll 4
    for (int kt = 0; kt < 16; kt++){
        int ko = kt*32 + q*8;
        uint2 ma[4][2];
        #pragma unroll
        for (int mt = 0; mt < 4; mt++){
            ma[mt][0] = *(const uint2*)(Mrow + (mt*16    )*HSTR*2 + ko);
            ma[mt][1] = *(const uint2*)(Mrow + (mt*16 + 8)*HSTR*2 + ko);
        }
        #pragma unroll
        for (int ot = 0; ot < 4; ot++){
            uint2 nb = *(const uint2*)(Nrow + (ot*8)*HSTR*2 + ko);
            #pragma unroll
            for (int mt = 0; mt < 4; mt++){
                mma_f16(acc[mt][ot][0], acc[mt][ot][1], acc[mt][ot][2], acc[mt][ot][3],
                        ma[mt][0].x, ma[mt][1].x, ma[mt][0].y, ma[mt][1].y, nb.x, nb.y);
            }
        }
    }

    #pragma unroll
    for (int mt = 0; mt < 4; mt++){
        #pragma unroll
        for (int ot = 0; ot < 4; ot++){
            int o = obase + ot*8 + 2*q;
            int n = n0 + mt*16 + g;
            __half* dst = d_F1h + ((size_t)b*Nn + n)*OO + o;
            *(__half2*)dst = __floats2half2_rn(acc[mt][ot][0], acc[mt][ot][1]);
            *(__half2*)(dst + 8*OO) = __floats2half2_rn(acc[mt][ot][2], acc[mt][ot][3]);
        }
    }
}

// ---------------- K3: stats of conv1 output, 2 bp per 256-thread block ----------------
__global__ void __launch_bounds__(256) k_stats1(const float* __restrict__ xyz,
                                                const float* __restrict__ rot,
                                                const float* __restrict__ W1){
    int sub = threadIdx.x >> 7;           // 0/1
    int t   = threadIdx.x & 127;
    int bp  = blockIdx.x*2 + sub;
    int b = bp >> 11;
    __shared__ int   idxs[2][32];
    __shared__ float gx[2][32], gy[2][32], gz[2][32];
    if (t < 32){
        int s = t;
        int i = d_idx[bp*Ss + s];
        idxs[sub][s] = i;
        const float* R = rot + (size_t)bp*9;
        const float* c = xyz + (size_t)bp*3;
        const float* q = xyz + ((size_t)b*Nn + i)*3;
        float vx = (q[0]-c[0]) / 0.05f;
        float vy = (q[1]-c[1]) / 0.05f;
        float vz = (q[2]-c[2]) / 0.05f;
        gx[sub][s] = vx*R[0] + vy*R[3] + vz*R[6];
        gy[sub][s] = vx*R[1] + vy*R[4] + vz*R[7];
        gz[sub][s] = vx*R[2] + vy*R[5] + vz*R[8];
    }
    __syncthreads();

    int c0 = t*2;
    float wa0 = W1[c0*K1+0],     wa1 = W1[c0*K1+1],     wa2 = W1[c0*K1+2];
    float wb0 = W1[(c0+1)*K1+0], wb1 = W1[(c0+1)*K1+1], wb2 = W1[(c0+1)*K1+2];
    const __half2* F1b2 = (const __half2*)(d_F1h + (size_t)b*Nn*OO);
    float lsa = 0.f, lqa = 0.f, lsb = 0.f, lqb = 0.f;
    #pragma unroll 8
    for (int s = 0; s < Ss; s++){
        __half2 hv = F1b2[(size_t)idxs[sub][s]*128 + t];
        float2 f = __half22float2(hv);
        float va = fmaf(wa0, gx[sub][s], fmaf(wa1, gy[sub][s], fmaf(wa2, gz[sub][s], f.x)));
        float vb = fmaf(wb0, gx[sub][s], fmaf(wb1, gy[sub][s], fmaf(wb2, gz[sub][s], f.y)));
        lsa += va;  lqa = fmaf(va, va, lqa);
        lsb += vb;  lqb = fmaf(vb, vb, lqb);
    }
    d_ps1s[bp*OO + c0]     = lsa;  d_ps1q[bp*OO + c0]     = lqa;
    d_ps1s[bp*OO + c0 + 1] = lsb;  d_ps1q[bp*OO + c0 + 1] = lqb;
}

// ---------------- deterministic two-level reduction ----------------
__global__ void k_red_a(int base){
    int which = base + blockIdx.y;               // 0..3
    const float* src = (which == 0) ? d_ps1s : (which == 1) ? d_ps1q
                     : (which == 2) ? d_ps2s : d_ps2q;
    float* dst = d_pp + which*(32*OO);
    int z = blockIdx.x;                          // 0..31
    int o = threadIdx.x;
    float s = 0.f;
    for (int k = 0; k < 256; k++)
        s += src[((size_t)(z*256 + k))*OO + o];
    dst[z*OO + o] = s;
}

__global__ void k_red_b(const float* __restrict__ gamma,
                        const float* __restrict__ beta){
    int o = threadIdx.x;
    const float* pps = d_pp + 2*(32*OO);
    const float* ppq = d_pp + 3*(32*OO);
    float s = 0.f, q = 0.f;
    for (int z = 0; z < 32; z++){ s += pps[z*OO + o]; q += ppq[z*OO + o]; }
    float mu  = s * INVCNT;
    float var = q * INVCNT - mu*mu;
    float sc  = rsqrtf(var + EPSf) * gamma[o];
    float sf  = beta[o] - mu*sc;
    d_scale2[o] = sc; d_shift2[o] = sf;
}

// smem layout (bytes) for conv2:
#define OFF_A   69632                 // h16: 128*HSTR*2 = 69632 before it
#define OFF_IDX 208896                // A: 256*HSTR*2 = 139264
#define OFF_GX  209408
#define OFF_GY  209920
#define OFF_GZ  210432
#define OFF_SC1 210944
#define OFF_SF1 211968
#define SMEMB   212992

// ---------------- K4: persistent conv2 — W2 resident, BN1 reduce fused in preamble ----------
__global__ void __launch_bounds__(512, 1) k_conv2(const float* __restrict__ xyz,
                                                  const float* __restrict__ rot,
                                                  const float* __restrict__ W1,
                                                  const float* __restrict__ gamma1,
                                                  const float* __restrict__ beta1){
    extern __shared__ __align__(16) char smraw[];
    __half* h16  = (__half*)smraw;                 // [128][HSTR]
    __half* Asm  = (__half*)(smraw + OFF_A);       // [256][HSTR]
    int*    idxs = (int*)(smraw + OFF_IDX);        // [128]
    float*  gxx  = (float*)(smraw + OFF_GX);
    float*  gyy  = (float*)(smraw + OFF_GY);
    float*  gzz  = (float*)(smraw + OFF_GZ);
    float*  s_sc1 = (float*)(smraw + OFF_SC1);     // [256]
    float*  s_sf1 = (float*)(smraw + OFF_SF1);     // [256]

    int tid = threadIdx.x;
    int lane = tid & 31, w = tid >> 5;
    int q = lane & 3, g = lane >> 2;
    int obase = (w & 7) * 32;                      // 8 warp-cols cover 256 o
    int warpS = (w >> 3) * 64;                     // 2 warp-rows cover 128 s

    // ---- load ALL of W2 into smem once ----
    #pragma unroll
    for (int k = 0; k < 16; k++){
        int i = tid + k*512;
        int row = i >> 5, seg = i & 31;
        uint32_t d = (uint32_t)__cvta_generic_to_shared(Asm + row*HSTR + seg*8);
        asm volatile("cp.async.cg.shared.global [%0], [%1], 16;\n"
                     :: "r"(d), "l"(d_W2h + (size_t)row*Cc + seg*8));
    }
    asm volatile("cp.async.commit_group;\n" ::: "memory");

    // ---- fused BN1 final reduce: scale1/shift1 into smem (overlaps cp.async) ----
    if (tid < 256){
        float s = 0.f, qv = 0.f;
        #pragma unroll 8
        for (int z = 0; z < 32; z++){
            s  += d_pp[z*OO + tid];
            qv += d_pp[32*OO + z*OO + tid];
        }
        float mu  = s * INVCNT;
        float var = qv * INVCNT - mu*mu;
        float sc  = rsqrtf(var + EPSf) * gamma1[tid];
        s_sc1[tid] = sc;
        s_sf1[tid] = beta1[tid] - mu*sc;
    }

    const char* Arow = (const char*)(Asm + (size_t)(obase + g)*HSTR);
    const char* Bsm  = (const char*)(h16 + (size_t)(warpS + g)*HSTR);

    for (int grp = blockIdx.x; grp < BP/4; grp += NSM){
        int bp0 = grp * 4;
        int b   = bp0 >> 11;

        if (tid < 128){
            int s  = tid;
            int bp = bp0 + (s >> 5);
            int i  = d_idx[bp*Ss + (s & 31)];
            idxs[s] = i;
            const float* R = rot + (size_t)bp*9;
            const float* c = xyz + (size_t)bp*3;
            const float* pt = xyz + ((size_t)b*Nn + i)*3;
            float vx = (pt[0]-c[0]) / 0.05f;
            float vy = (pt[1]-c[1]) / 0.05f;
            float vz = (pt[2]-c[2]) / 0.05f;
            gxx[s] = vx*R[0] + vy*R[3] + vz*R[6];
            gyy[s] = vx*R[1] + vy*R[4] + vz*R[7];
            gzz[s] = vx*R[2] + vy*R[5] + vz*R[8];
        }
        __syncthreads();

        {
            int cpair = tid & 127;
            int c0    = cpair*2;
            int sbase = (tid >> 7) * 32;
            int p     = kperm(c0);
            float wa0 = W1[c0*K1+0],     wa1 = W1[c0*K1+1],     wa2 = W1[c0*K1+2];
            float wb0 = W1[(c0+1)*K1+0], wb1 = W1[(c0+1)*K1+1], wb2 = W1[(c0+1)*K1+2];
            float sca = s_sc1[c0],   sfa = s_sf1[c0];
            float scb = s_sc1[c0+1], sfb = s_sf1[c0+1];
            const __half2* F1b2 = (const __half2*)(d_F1h + (size_t)b*Nn*OO);
            #pragma unroll 8
            for (int ds = 0; ds < 32; ds++){
                int s = sbase + ds;
                float2 f = __half22float2(F1b2[(size_t)idxs[s]*128 + cpair]);
                float va = fmaf(wa0, gxx[s], fmaf(wa1, gyy[s], fmaf(wa2, gzz[s], f.x)));
                float vb = fmaf(wb0, gxx[s], fmaf(wb1, gyy[s], fmaf(wb2, gzz[s], f.y)));
                va = fmaxf(fmaf(va, sca, sfa), 0.f);
                vb = fmaxf(fmaf(vb, scb, sfb), 0.f);
                *(__half2*)(h16 + s*HSTR + p) = __floats2half2_rn(va, vb);
            }
        }
        asm volatile("cp.async.wait_group 0;\n" ::: "memory");
        __syncthreads();

        float acc[2][8][4];
        #pragma unroll
        for (int i = 0; i < 2; i++)
            #pragma unroll
            for (int j = 0; j < 8; j++)
                #pragma unroll
                for (int k = 0; k < 4; k++) acc[i][j][k] = 0.f;

        #pragma unroll 4
        for (int kt = 0; kt < 16; kt++){
            uint2 fa0 = *(const uint2*)(Arow +             0 + kt*32 + q*8);
            uint2 fa1 = *(const uint2*)(Arow +  8*HSTR*2      + kt*32 + q*8);
            uint2 fa2 = *(const uint2*)(Arow + 16*HSTR*2      + kt*32 + q*8);
            uint2 fa3 = *(const uint2*)(Arow + 24*HSTR*2      + kt*32 + q*8);
            #pragma unroll
            for (int j = 0; j < 8; j++){
                uint2 bv = *(const uint2*)(Bsm + j*(8*HSTR*2) + kt*32 + q*8);
                mma_f16(acc[0][j][0], acc[0][j][1], acc[0][j][2], acc[0][j][3],
                        fa0.x, fa1.x, fa0.y, fa1.y, bv.x, bv.y);
                mma_f16(acc[1][j][0], acc[1][j][1], acc[1][j][2], acc[1][j][3],
                        fa2.x, fa3.x, fa2.y, fa3.y, bv.x, bv.y);
            }
        }

        #pragma unroll
        for (int half = 0; half < 2; half++){
            int bp = bp0 + 2*(w >> 3) + half;
            #pragma unroll
            for (int i = 0; i < 2; i++){
                float s0=0.f, q0=0.f, mx0=-3.4e38f, mn0=3.4e38f;
                float s1=0.f, q1=0.f, mx1=-3.4e38f, mn1=3.4e38f;
                #pragma unroll
                for (int j4 = 0; j4 < 4; j4++){
                    const float* a = acc[i][half*4 + j4];
                    s0 += a[0] + a[1];
                    q0  = fmaf(a[0], a[0], fmaf(a[1], a[1], q0));
                    mx0 = fmaxf(mx0, fmaxf(a[0], a[1]));
                    mn0 = fminf(mn0, fminf(a[0], a[1]));
                    s1 += a[2] + a[3];
                    q1  = fmaf(a[2], a[2], fmaf(a[3], a[3], q1));
                    mx1 = fmaxf(mx1, fmaxf(a[2], a[3]));
                    mn1 = fminf(mn1, fminf(a[2], a[3]));
                }
                #pragma unroll
                for (int msk = 1; msk <= 2; msk <<= 1){
                    s0 += __shfl_xor_sync(0xffffffffu, s0, msk);
                    q0 += __shfl_xor_sync(0xffffffffu, q0, msk);
                    mx0 = fmaxf(mx0, __shfl_xor_sync(0xffffffffu, mx0, msk));
                    mn0 = fminf(mn0, __shfl_xor_sync(0xffffffffu, mn0, msk));
                    s1 += __shfl_xor_sync(0xffffffffu, s1, msk);
                    q1 += __shfl_xor_sync(0xffffffffu, q1, msk);
                    mx1 = fmaxf(mx1, __shfl_xor_sync(0xffffffffu, mx1, msk));
                    mn1 = fminf(mn1, __shfl_xor_sync(0xffffffffu, mn1, msk));
                }
                if (q == 0){
                    int o0 = obase + 16*i + g;
                    size_t ix0 = (size_t)bp*OO + o0;
                    d_ps2s[ix0] = s0; d_ps2q[ix0] = q0; d_mx2[ix0] = mx0; d_mn2[ix0] = mn0;
                    size_t ix1 = ix0 + 8;
                    d_ps2s[ix1] = s1; d_ps2q[ix1] = q1; d_mx2[ix1] = mx1; d_mn2[ix1] = mn1;
                }
            }
        }
    }
}

// ---------------- K5: BN2 + relu + max via monotonicity, transpose-write ----------------
__global__ void __launch_bounds__(256) k_final(float* __restrict__ out){
    int blk = blockIdx.x;                 // 256 blocks, 32 p's each
    int bp0 = blk * 32;
    int b = bp0 >> 11;
    int pbase = bp0 & 2047;
    int tid = threadIdx.x;
    __shared__ float sh[256*33];

    int o = tid;
    float sc = d_scale2[o], sf = d_shift2[o];
    for (int p = 0; p < 32; p++){
        size_t ix = (size_t)(bp0 + p)*OO + o;
        float mx = d_mx2[ix], mn = d_mn2[ix];
        float m = (sc >= 0.f) ? mx : mn;
        sh[o*33 + p] = fmaxf(fmaf(m, sc, sf), 0.f);
    }
    __syncthreads();

    int p   = tid & 31;
    int og0 = (tid >> 5) * 32;
    #pragma unroll
    for (int k = 0; k < 32; k++){
        int o2 = og0 + k;
        out[((size_t)(b*OO + o2))*Nn + pbase + p] = sh[o2*33 + p];
    }
}

// ---------------- launcher ----------------
extern "C" void kernel_launch(void* const* d_in, const int* in_sizes, int n_in,
                              void* d_out, int out_size){
    (void)in_sizes; (void)n_in; (void)out_size;
    const float* xyz  = (const float*)d_in[0];
    const float* feat = (const float*)d_in[1];
    const float* rot  = (const float*)d_in[2];
    const float* W1   = (const float*)d_in[3];
    const float* g1   = (const float*)d_in[4];
    const float* b1   = (const float*)d_in[5];
    const float* W2   = (const float*)d_in[6];
    const float* g2   = (const float*)d_in[7];
    const float* b2   = (const float*)d_in[8];
    float* out = (float*)d_out;

    static bool s_init = false;
    static cudaStream_t s2;
    static cudaEvent_t evA, evB;
    if (!s_init){
        cudaStreamCreateWithFlags(&s2, cudaStreamNonBlocking);
        cudaEventCreateWithFlags(&evA, cudaEventDisableTiming);
        cudaEventCreateWithFlags(&evB, cudaEventDisableTiming);
        cudaFuncSetAttribute(k_conv2, cudaFuncAttributeMaxDynamicSharedMemorySize, SMEMB);
        cudaFuncSetAttribute(k_F1mma, cudaFuncAttributeMaxDynamicSharedMemorySize, F1_SMEM);
        s_init = true;
    }

    // fork: k_idx on side stream, concurrent with weight prep + F1 GEMM
    cudaEventRecord(evA, 0);
    cudaStreamWaitEvent(s2, evA, 0);
    k_idx<<<BP/8, 256, 0, s2>>>(xyz, rot);
    cudaEventRecord(evB, s2);

    k_wtr  <<<256 + 2048, 256>>>(W1, W2, feat);
    k_F1mma<<<128, 256, F1_SMEM>>>();

    // join: stats1 needs idx + F1
    cudaStreamWaitEvent(0, evB, 0);

    k_stats1<<<BP/2, 256>>>(xyz, rot, W1);
    k_red_a <<<dim3(32,2), 256>>>(0);
    k_conv2 <<<NSM, 512, SMEMB>>>(xyz, rot, W1, g1, b1);
    k_red_a <<<dim3(32,2), 256>>>(2);
    k_red_b <<<1, 256>>>(g2, b2);
    k_final <<<BP/32, 256>>>(out);
}

// round 12
// speedup vs baseline: 1.5692x; 1.0292x over previous
#include <cuda_runtime.h>
#include <cuda_fp16.h>
#include <cstdint>

#define Bb 4
#define Nn 2048
#define Cc 256
#define OO 256
#define Ss 32
#define BP (Bb*Nn)            // 8192
#define Ee (BP*Ss)            // 262144
#define K1 259

#define HMINf (-0.02f)
#define HMAXf (0.04f)
#define EPSf  (1e-5f)
#define INVCNT (1.0f/(float)Ee)
#define NSM 148

// ---------------- static device scratch (allocation-free rule) ----------------
__device__ __half d_W2h [OO*Cc];            // fp16 W2, k-slot-permuted: [o][p(c)]
__device__ __half d_W1h [OO*Cc];            // fp16 W1 feature part, k-slot-permuted
__device__ __half d_ftT [(size_t)Bb*Nn*Cc]; // feat transposed fp16: [b][n][p(c)]
__device__ int    d_idx [BP*Ss];            // neighbor indices
__device__ __half d_F1h [(size_t)Bb*Nn*OO]; // F1[b][n][o] fp16  (4MB, L2-resident)
__device__ float  d_ps1s[BP*OO], d_ps1q[BP*OO];   // stage-1 partial sums
__device__ float  d_ps2s[BP*OO], d_ps2q[BP*OO];   // stage-2 partial sums
__device__ float  d_mx2 [BP*OO], d_mn2 [BP*OO];   // per-(bp,o) max/min of y2 over s
__device__ float  d_pp  [4*32*OO];                // level-2 partials
__device__ float  d_scale2[OO], d_shift2[OO];

// k-slot permutation: one thread's 4-half mma fragment = one contiguous 8B load.
__device__ __forceinline__ int kperm(int c){
    int c16 = c & 15;
    int q  = (c16 & 7) >> 1;
    int r  = c16 & 1;
    int hi = (c16 >> 3) & 1;
    return (c & ~15) | (q*4 + hi*2 + r);
}

// ---------------- K0: fused weight prep + feat transpose ----------------
__global__ void __launch_bounds__(256) k_wtr(const float* __restrict__ W1,
                                             const float* __restrict__ W2,
                                             const float* __restrict__ feat){
    if (blockIdx.x < 256){
        int i = blockIdx.x*256 + threadIdx.x;      // i = o*256 + c
        int o = i >> 8, c = i & 255;
        d_W1h[o*Cc + kperm(c)] = __float2half_rn(W1[o*K1 + 3 + c]);
        d_W2h[o*Cc + kperm(c)] = __float2half_rn(W2[i]);
        return;
    }
    int blk = blockIdx.x - 256;           // b(4) x ct(8) x nt(64)
    int b  = blk >> 9;
    int ct = (blk >> 6) & 7;
    int nt = blk & 63;
    int n0 = nt*32, c0 = ct*32;
    __shared__ float tsh[32][33];
    int t = threadIdx.x;
    {
        int cr = t >> 3, nq = (t & 7)*4;
        const float4 v = *(const float4*)(feat + ((size_t)b*Cc + c0 + cr)*Nn + n0 + nq);
        tsh[cr][nq+0] = v.x; tsh[cr][nq+1] = v.y; tsh[cr][nq+2] = v.z; tsh[cr][nq+3] = v.w;
    }
    __syncthreads();
    {
        int n = t >> 3, cl = (t & 7)*4;
        __half* dst = d_ftT + ((size_t)b*Nn + n0 + n)*Cc;
        #pragma unroll
        for (int w = 0; w < 2; w++){
            int cg = c0 + cl + w*2;            // even
            __half2 hv = __floats2half2_rn(tsh[cl + w*2][n], tsh[cl + w*2 + 1][n]);
            *(__half2*)(dst + kperm(cg)) = hv;
        }
    }
}

// ---------------- K1: cylinder query (one warp per (b,p)) ----------------
__global__ void k_idx(const float* __restrict__ xyz, const float* __restrict__ rot){
    int bp   = blockIdx.x*8 + (threadIdx.x >> 5);
    int lane = threadIdx.x & 31;
    int b = bp >> 11;
    const float* R = rot + (size_t)bp*9;
    float r00=R[0],r01=R[1],r02=R[2],r10=R[3],r11=R[4],r12=R[5],r20=R[6],r21=R[7],r22=R[8];
    const float* cc = xyz + (size_t)bp*3;
    float cx=cc[0], cy=cc[1], cz=cc[2];
    const float R2v = (float)(0.05*0.05);
    int count = 0, firstn = 0;
    bool have = false;
    for (int base = 0; base < Nn && count < Ss; base += 32){
        int n = base + lane;
        const float* q = xyz + ((size_t)b*Nn + n)*3;
        float dx=q[0]-cx, dy=q[1]-cy, dz=q[2]-cz;
        float a0 = r00*dx + r01*dy + r02*dz;
        float a1 = r10*dx + r11*dy + r12*dz;
        float a2 = r20*dx + r21*dy + r22*dz;
        bool m = (a1*a1 + a2*a2 < R2v) & (a0 > HMINf) & (a0 < HMAXf);
        unsigned bal = __ballot_sync(0xffffffffu, m);
        if (!have && bal){ firstn = base + (__ffs(bal) - 1); have = true; }
        int pre = __popc(bal & ((1u << lane) - 1u));
        if (m && count + pre < Ss) d_idx[bp*Ss + count + pre] = n;
        count += __popc(bal);
    }
    if (count < Ss){
        for (int j = count + lane; j < Ss; j += 32) d_idx[bp*Ss + j] = firstn;
    }
}

// ---------------- fp16 mma helper ----------------
__device__ __forceinline__ void mma_f16(float& d0, float& d1, float& d2, float& d3,
                                        uint32_t a0, uint32_t a1, uint32_t a2, uint32_t a3,
                                        uint32_t b0, uint32_t b1){
    asm volatile("mma.sync.aligned.m16n8k16.row.col.f32.f16.f16.f32 "
                 "{%0,%1,%2,%3}, {%4,%5,%6,%7}, {%8,%9}, {%0,%1,%2,%3};\n"
                 : "+f"(d0), "+f"(d1), "+f"(d2), "+f"(d3)
                 : "r"(a0), "r"(a1), "r"(a2), "r"(a3), "r"(b0), "r"(b1));
}

#define HSTR 272   // halfs: 136 words == 8 (mod 32) -> conflict-free LDS.64 frags

// ---------------- K2: F1 on tensor cores ----------------
#define F1_SMEM (34816 + 139264)
__global__ void __launch_bounds__(256) k_F1mma(){
    extern __shared__ __align__(16) char sm1[];
    __half* Mt = (__half*)sm1;                   // ftT tile [64][HSTR]
    __half* Nw = (__half*)(sm1 + 34816);         // W1h [256][HSTR]
    int tid = threadIdx.x;
    int blk = blockIdx.x;                        // 128 = b(4) x nt(32)
    int b  = blk >> 5;
    int n0 = (blk & 31) * 64;

    #pragma unroll
    for (int k = 0; k < 32; k++){
        int i = tid + k*256;
        int row = i >> 5, seg = i & 31;
        uint32_t d = (uint32_t)__cvta_generic_to_shared(Nw + row*HSTR + seg*8);
        asm volatile("cp.async.cg.shared.global [%0], [%1], 16;\n"
                     :: "r"(d), "l"(d_W1h + (size_t)row*Cc + seg*8));
    }
    #pragma unroll
    for (int k = 0; k < 8; k++){
        int i = tid + k*256;
        int row = i >> 5, seg = i & 31;
        uint32_t d = (uint32_t)__cvta_generic_to_shared(Mt + row*HSTR + seg*8);
        asm volatile("cp.async.cg.shared.global [%0], [%1], 16;\n"
                     :: "r"(d), "l"(d_ftT + ((size_t)b*Nn + n0 + row)*Cc + seg*8));
    }
    asm volatile("cp.async.commit_group;\n" ::: "memory");
    asm volatile("cp.async.wait_group 0;\n" ::: "memory");
    __syncthreads();

    int lane = tid & 31, w = tid >> 5;
    int q = lane & 3, g = lane >> 2;
    int obase = w * 32;

    float acc[4][4][4];
    #pragma unroll
    for (int mt = 0; mt < 4; mt++)
        #pragma unroll
        for (int ot = 0; ot < 4; ot++)
            #pragma unroll
            for (int k = 0; k < 4; k++) acc[mt][ot][k] = 0.f;

    const char* Mrow = (const char*)(Mt + (size_t)g*HSTR);
    const char* Nrow = (const char*)(Nw + (size_t)(obase + g)*HSTR);

    #pragma unroll 4
    for (int kt = 0; kt < 16; kt++){
        int ko = kt*32 + q*8;
        uint2 ma[4][2];
        #pragma unroll
        for (int mt = 0; mt < 4; mt++){
            ma[mt][0] = *(const uint2*)(Mrow + (mt*16    )*HSTR*2 + ko);
            ma[mt][1] = *(const uint2*)(Mrow + (mt*16 + 8)*HSTR*2 + ko);
        }
        #pragma unroll
        for (int ot = 0; ot < 4; ot++){
            uint2 nb = *(const uint2*)(Nrow + (ot*8)*HSTR*2 + ko);
            #pragma unroll
            for (int mt = 0; mt < 4; mt++){
                mma_f16(acc[mt][ot][0], acc[mt][ot][1], acc[mt][ot][2], acc[mt][ot][3],
                        ma[mt][0].x, ma[mt][1].x, ma[mt][0].y, ma[mt][1].y, nb.x, nb.y);
            }
        }
    }

    #pragma unroll
    for (int mt = 0; mt < 4; mt++){
        #pragma unroll
        for (int ot = 0; ot < 4; ot++){
            int o = obase + ot*8 + 2*q;
            int n = n0 + mt*16 + g;
            __half* dst = d_F1h + ((size_t)b*Nn + n)*OO + o;
            *(__half2*)dst = __floats2half2_rn(acc[mt][ot][0], acc[mt][ot][1]);
            *(__half2*)(dst + 8*OO) = __floats2half2_rn(acc[mt][ot][2], acc[mt][ot][3]);
        }
    }
}

// ---------------- K3: stats of conv1 output, 2 bp per 256-thread block ----------------
__global__ void __launch_bounds__(256) k_stats1(const float* __restrict__ xyz,
                                                const float* __restrict__ rot,
                                                const float* __restrict__ W1){
    int sub = threadIdx.x >> 7;           // 0/1
    int t   = threadIdx.x & 127;
    int bp  = blockIdx.x*2 + sub;
    int b = bp >> 11;
    __shared__ int   idxs[2][32];
    __shared__ float gx[2][32], gy[2][32], gz[2][32];
    if (t < 32){
        int s = t;
        int i = d_idx[bp*Ss + s];
        idxs[sub][s] = i;
        const float* R = rot + (size_t)bp*9;
        const float* c = xyz + (size_t)bp*3;
        const float* q = xyz + ((size_t)b*Nn + i)*3;
        float vx = (q[0]-c[0]) / 0.05f;
        float vy = (q[1]-c[1]) / 0.05f;
        float vz = (q[2]-c[2]) / 0.05f;
        gx[sub][s] = vx*R[0] + vy*R[3] + vz*R[6];
        gy[sub][s] = vx*R[1] + vy*R[4] + vz*R[7];
        gz[sub][s] = vx*R[2] + vy*R[5] + vz*R[8];
    }
    __syncthreads();

    int c0 = t*2;
    float wa0 = W1[c0*K1+0],     wa1 = W1[c0*K1+1],     wa2 = W1[c0*K1+2];
    float wb0 = W1[(c0+1)*K1+0], wb1 = W1[(c0+1)*K1+1], wb2 = W1[(c0+1)*K1+2];
    const __half2* F1b2 = (const __half2*)(d_F1h + (size_t)b*Nn*OO);
    float lsa = 0.f, lqa = 0.f, lsb = 0.f, lqb = 0.f;
    #pragma unroll 8
    for (int s = 0; s < Ss; s++){
        __half2 hv = F1b2[(size_t)idxs[sub][s]*128 + t];
        float2 f = __half22float2(hv);
        float va = fmaf(wa0, gx[sub][s], fmaf(wa1, gy[sub][s], fmaf(wa2, gz[sub][s], f.x)));
        float vb = fmaf(wb0, gx[sub][s], fmaf(wb1, gy[sub][s], fmaf(wb2, gz[sub][s], f.y)));
        lsa += va;  lqa = fmaf(va, va, lqa);
        lsb += vb;  lqb = fmaf(vb, vb, lqb);
    }
    d_ps1s[bp*OO + c0]     = lsa;  d_ps1q[bp*OO + c0]     = lqa;
    d_ps1s[bp*OO + c0 + 1] = lsb;  d_ps1q[bp*OO + c0 + 1] = lqb;
}

// ---------------- deterministic two-level reduction ----------------
__global__ void k_red_a(int base){
    int which = base + blockIdx.y;               // 0..3
    const float* src = (which == 0) ? d_ps1s : (which == 1) ? d_ps1q
                     : (which == 2) ? d_ps2s : d_ps2q;
    float* dst = d_pp + which*(32*OO);
    int z = blockIdx.x;                          // 0..31
    int o = threadIdx.x;
    float s = 0.f;
    for (int k = 0; k < 256; k++)
        s += src[((size_t)(z*256 + k))*OO + o];
    dst[z*OO + o] = s;
}

__global__ void k_red_b(const float* __restrict__ gamma,
                        const float* __restrict__ beta){
    int o = threadIdx.x;
    const float* pps = d_pp + 2*(32*OO);
    const float* ppq = d_pp + 3*(32*OO);
    float s = 0.f, q = 0.f;
    for (int z = 0; z < 32; z++){ s += pps[z*OO + o]; q += ppq[z*OO + o]; }
    float mu  = s * INVCNT;
    float var = q * INVCNT - mu*mu;
    float sc  = rsqrtf(var + EPSf) * gamma[o];
    float sf  = beta[o] - mu*sc;
    d_scale2[o] = sc; d_shift2[o] = sf;
}

// smem layout (bytes) for conv2 (double-buffered h, 2-bp groups):
#define OFF_A   69632                 // 2 x h[64][HSTR] halfs = 69632 before it
#define OFF_IDX 208896                // A: 256*HSTR*2 = 139264
#define OFF_G   209408                // 2 x 3 x 64 floats = 1536
#define OFF_SC1 210944
#define OFF_SF1 211968
#define SMEMB   212992

// geometry for one 2-bp group into the given buffers (threads 0..63)
__device__ __forceinline__ void geom2(const float* __restrict__ xyz,
                                      const float* __restrict__ rot,
                                      int grp, int tid, int* idxd,
                                      float* gx, float* gy, float* gz){
    if (tid < 64){
        int s  = tid;
        int bp = grp*2 + (s >> 5);
        int b  = bp >> 11;
        int i  = d_idx[bp*Ss + (s & 31)];
        idxd[s] = i;
        const float* R = rot + (size_t)bp*9;
        const float* c = xyz + (size_t)bp*3;
        const float* pt = xyz + ((size_t)b*Nn + i)*3;
        float vx = (pt[0]-c[0]) / 0.05f;
        float vy = (pt[1]-c[1]) / 0.05f;
        float vz = (pt[2]-c[2]) / 0.05f;
        gx[s] = vx*R[0] + vy*R[3] + vz*R[6];
        gy[s] = vx*R[1] + vy*R[4] + vz*R[7];
        gz[s] = vx*R[2] + vy*R[5] + vz*R[8];
    }
}

// build h tile for one 2-bp group (all 512 threads; 2 channels x 16 s each)
__device__ __forceinline__ void hbuild2(const float* __restrict__ W1, __half* hdst,
                                        const int* idxd, const float* gx,
                                        const float* gy, const float* gz,
                                        const float* s_sc1, const float* s_sf1,
                                        int grp, int tid){
    int cpair = tid & 127;
    int c0    = cpair*2;
    int sbase = (tid >> 7) * 16;
    int b     = (grp*2) >> 11;
    int p     = kperm(c0);
    float wa0 = W1[c0*K1+0],     wa1 = W1[c0*K1+1],     wa2 = W1[c0*K1+2];
    float wb0 = W1[(c0+1)*K1+0], wb1 = W1[(c0+1)*K1+1], wb2 = W1[(c0+1)*K1+2];
    float sca = s_sc1[c0],   sfa = s_sf1[c0];
    float scb = s_sc1[c0+1], sfb = s_sf1[c0+1];
    const __half2* F1b2 = (const __half2*)(d_F1h + (size_t)b*Nn*OO);
    #pragma unroll 4
    for (int ds = 0; ds < 16; ds++){
        int s = sbase + ds;
        float2 f = __half22float2(F1b2[(size_t)idxd[s]*128 + cpair]);
        float va = fmaf(wa0, gx[s], fmaf(wa1, gy[s], fmaf(wa2, gz[s], f.x)));
        float vb = fmaf(wb0, gx[s], fmaf(wb1, gy[s], fmaf(wb2, gz[s], f.y)));
        va = fmaxf(fmaf(va, sca, sfa), 0.f);
        vb = fmaxf(fmaf(vb, scb, sfb), 0.f);
        *(__half2*)(hdst + s*HSTR + p) = __floats2half2_rn(va, vb);
    }
}

// ---------------- K4: persistent conv2, double-buffered h (2-bp groups) ----------------
__global__ void __launch_bounds__(512, 1) k_conv2(const float* __restrict__ xyz,
                                                  const float* __restrict__ rot,
                                                  const float* __restrict__ W1,
                                                  const float* __restrict__ gamma1,
                                                  const float* __restrict__ beta1){
    extern __shared__ __align__(16) char smraw[];
    __half* h16  = (__half*)smraw;                 // 2 x [64][HSTR]
    __half* Asm  = (__half*)(smraw + OFF_A);       // [256][HSTR]
    int*    idxb = (int*)(smraw + OFF_IDX);        // 2 x [64]
    float*  gbuf = (float*)(smraw + OFF_G);        // 2 x 3 x [64]
    float*  s_sc1 = (float*)(smraw + OFF_SC1);     // [256]
    float*  s_sf1 = (float*)(smraw + OFF_SF1);     // [256]

    int tid = threadIdx.x;
    int lane = tid & 31, w = tid >> 5;
    int q = lane & 3, g = lane >> 2;
    int obase = (w & 7) * 32;                      // 8 warp-cols cover 256 o
    int warpS = (w >> 3) * 32;                     // 2 warp-rows cover 64 s (= 2 bp)

    // ---- load ALL of W2 into smem once ----
    #pragma unroll
    for (int k = 0; k < 16; k++){
        int i = tid + k*512;
        int row = i >> 5, seg = i & 31;
        uint32_t d = (uint32_t)__cvta_generic_to_shared(Asm + row*HSTR + seg*8);
        asm volatile("cp.async.cg.shared.global [%0], [%1], 16;\n"
                     :: "r"(d), "l"(d_W2h + (size_t)row*Cc + seg*8));
    }
    asm volatile("cp.async.commit_group;\n" ::: "memory");

    // ---- fused BN1 final reduce (overlaps cp.async) ----
    if (tid < 256){
        float s = 0.f, qv = 0.f;
        #pragma unroll 8
        for (int z = 0; z < 32; z++){
            s  += d_pp[z*OO + tid];
            qv += d_pp[32*OO + z*OO + tid];
        }
        float mu  = s * INVCNT;
        float var = qv * INVCNT - mu*mu;
        float sc  = rsqrtf(var + EPSf) * gamma1[tid];
        s_sc1[tid] = sc;
        s_sf1[tid] = beta1[tid] - mu*sc;
    }

    const char* Arow = (const char*)(Asm + (size_t)(obase + g)*HSTR);
    const int NG = BP/2;                           // 4096 groups of 2 bp

    // prologue: geom(g0) ; sync ; hbuild(g0) + geom(g1) ; sync
    int g0 = blockIdx.x;
    geom2(xyz, rot, g0, tid, idxb, gbuf, gbuf+128, gbuf+256);
    __syncthreads();
    hbuild2(W1, h16, idxb, gbuf, gbuf+128, gbuf+256, s_sc1, s_sf1, g0, tid);
    if (g0 + NSM < NG)
        geom2(xyz, rot, g0 + NSM, tid, idxb+64, gbuf+64, gbuf+192, gbuf+320);
    asm volatile("cp.async.wait_group 0;\n" ::: "memory");
    __syncthreads();

    int par = 0;
    for (int gi = g0; gi < NG; gi += NSM){
        int np = par ^ 1;
        // independent work in one region: hbuild(next) + geom(next2) + mma(cur)
        if (gi + NSM < NG)
            hbuild2(W1, h16 + np*64*HSTR, idxb + np*64,
                    gbuf + np*64, gbuf + 128 + np*64, gbuf + 256 + np*64,
                    s_sc1, s_sf1, gi + NSM, tid);
        if (gi + 2*NSM < NG)
            geom2(xyz, rot, gi + 2*NSM, tid, idxb + par*64,
                  gbuf + par*64, gbuf + 128 + par*64, gbuf + 256 + par*64);

        const char* Bsm = (const char*)(h16 + (size_t)par*64*HSTR + (size_t)(warpS + g)*HSTR);
        float acc[2][4][4];
        #pragma unroll
        for (int i = 0; i < 2; i++)
            #pragma unroll
            for (int j = 0; j < 4; j++)
                #pragma unroll
                for (int k = 0; k < 4; k++) acc[i][j][k] = 0.f;

        #pragma unroll 4
        for (int kt = 0; kt < 16; kt++){
            uint2 fa0 = *(const uint2*)(Arow +             0 + kt*32 + q*8);
            uint2 fa1 = *(const uint2*)(Arow +  8*HSTR*2      + kt*32 + q*8);
            uint2 fa2 = *(const uint2*)(Arow + 16*HSTR*2      + kt*32 + q*8);
            uint2 fa3 = *(const uint2*)(Arow + 24*HSTR*2      + kt*32 + q*8);
            #pragma unroll
            for (int j = 0; j < 4; j++){
                uint2 bv = *(const uint2*)(Bsm + j*(8*HSTR*2) + kt*32 + q*8);
                mma_f16(acc[0][j][0], acc[0][j][1], acc[0][j][2], acc[0][j][3],
                        fa0.x, fa1.x, fa0.y, fa1.y, bv.x, bv.y);
                mma_f16(acc[1][j][0], acc[1][j][1], acc[1][j][2], acc[1][j][3],
                        fa2.x, fa3.x, fa2.y, fa3.y, bv.x, bv.y);
            }
        }

        // epilogue: this warp's 32-s row is exactly one bp
        int bp = gi*2 + (w >> 3);
        #pragma unroll
        for (int i = 0; i < 2; i++){
            float s0=0.f, q0=0.f, mx0=-3.4e38f, mn0=3.4e38f;   // row g
            float s1=0.f, q1=0.f, mx1=-3.4e38f, mn1=3.4e38f;   // row g+8
            #pragma unroll
            for (int j4 = 0; j4 < 4; j4++){
                const float* a = acc[i][j4];
                s0 += a[0] + a[1];
                q0  = fmaf(a[0], a[0], fmaf(a[1], a[1], q0));
                mx0 = fmaxf(mx0, fmaxf(a[0], a[1]));
                mn0 = fminf(mn0, fminf(a[0], a[1]));
                s1 += a[2] + a[3];
                q1  = fmaf(a[2], a[2], fmaf(a[3], a[3], q1));
                mx1 = fmaxf(mx1, fmaxf(a[2], a[3]));
                mn1 = fminf(mn1, fminf(a[2], a[3]));
            }
            #pragma unroll
            for (int msk = 1; msk <= 2; msk <<= 1){
                s0 += __shfl_xor_sync(0xffffffffu, s0, msk);
                q0 += __shfl_xor_sync(0xffffffffu, q0, msk);
                mx0 = fmaxf(mx0, __shfl_xor_sync(0xffffffffu, mx0, msk));
                mn0 = fminf(mn0, __shfl_xor_sync(0xffffffffu, mn0, msk));
                s1 += __shfl_xor_sync(0xffffffffu, s1, msk);
                q1 += __shfl_xor_sync(0xffffffffu, q1, msk);
                mx1 = fmaxf(mx1, __shfl_xor_sync(0xffffffffu, mx1, msk));
                mn1 = fminf(mn1, __shfl_xor_sync(0xffffffffu, mn1, msk));
            }
            if (q == 0){
                int o0 = obase + 16*i + g;
                size_t ix0 = (size_t)bp*OO + o0;
                d_ps2s[ix0] = s0; d_ps2q[ix0] = q0; d_mx2[ix0] = mx0; d_mn2[ix0] = mn0;
                size_t ix1 = ix0 + 8;
                d_ps2s[ix1] = s1; d_ps2q[ix1] = q1; d_mx2[ix1] = mx1; d_mn2[ix1] = mn1;
            }
        }
        __syncthreads();
        par = np;
    }
}

// ---------------- K5: BN2 + relu + max via monotonicity, transpose-write ----------------
__global__ void __launch_bounds__(256) k_final(float* __restrict__ out){
    int blk = blockIdx.x;                 // 256 blocks, 32 p's each
    int bp0 = blk * 32;
    int b = bp0 >> 11;
    int pbase = bp0 & 2047;
    int tid = threadIdx.x;
    __shared__ float sh[256*33];

    int o = tid;
    float sc = d_scale2[o], sf = d_shift2[o];
    for (int p = 0; p < 32; p++){
        size_t ix = (size_t)(bp0 + p)*OO + o;
        float mx = d_mx2[ix], mn = d_mn2[ix];
        float m = (sc >= 0.f) ? mx : mn;
        sh[o*33 + p] = fmaxf(fmaf(m, sc, sf), 0.f);
    }
    __syncthreads();

    int p   = tid & 31;
    int og0 = (tid >> 5) * 32;
    #pragma unroll
    for (int k = 0; k < 32; k++){
        int o2 = og0 + k;
        out[((size_t)(b*OO + o2))*Nn + pbase + p] = sh[o2*33 + p];
    }
}

// ---------------- launcher ----------------
extern "C" void kernel_launch(void* const* d_in, const int* in_sizes, int n_in,
                              void* d_out, int out_size){
    (void)in_sizes; (void)n_in; (void)out_size;
    const float* xyz  = (const float*)d_in[0];
    const float* feat = (const float*)d_in[1];
    const float* rot  = (const float*)d_in[2];
    const float* W1   = (const float*)d_in[3];
    const float* g1   = (const float*)d_in[4];
    const float* b1   = (const float*)d_in[5];
    const float* W2   = (const float*)d_in[6];
    const float* g2   = (const float*)d_in[7];
    const float* b2   = (const float*)d_in[8];
    float* out = (float*)d_out;

    static bool s_init = false;
    static cudaStream_t s2;
    static cudaEvent_t evA, evB;
    if (!s_init){
        cudaStreamCreateWithFlags(&s2, cudaStreamNonBlocking);
        cudaEventCreateWithFlags(&evA, cudaEventDisableTiming);
        cudaEventCreateWithFlags(&evB, cudaEventDisableTiming);
        cudaFuncSetAttribute(k_conv2, cudaFuncAttributeMaxDynamicSharedMemorySize, SMEMB);
        cudaFuncSetAttribute(k_F1mma, cudaFuncAttributeMaxDynamicSharedMemorySize, F1_SMEM);
        s_init = true;
    }

    // fork: k_idx on side stream, concurrent with weight prep + F1 GEMM
    cudaEventRecord(evA, 0);
    cudaStreamWaitEvent(s2, evA, 0);
    k_idx<<<BP/8, 256, 0, s2>>>(xyz, rot);
    cudaEventRecord(evB, s2);

    k_wtr  <<<256 + 2048, 256>>>(W1, W2, feat);
    k_F1mma<<<128, 256, F1_SMEM>>>();

    // join: stats1 needs idx + F1
    cudaStreamWaitEvent(0, evB, 0);

    k_stats1<<<BP/2, 256>>>(xyz, rot, W1);
    k_red_a <<<dim3(32,2), 256>>>(0);
    k_conv2 <<<NSM, 512, SMEMB>>>(xyz, rot, W1, g1, b1);
    k_red_a <<<dim3(32,2), 256>>>(2);
    k_red_b <<<1, 256>>>(g2, b2);
    k_final <<<BP/32, 256>>>(out);
}